// round 4
// baseline (speedup 1.0000x reference)
#include <cuda_runtime.h>
#include <cstdint>
#include <cub/cub.cuh>

#define VN_    50000
#define FN_    100000
#define S3_    (3*FN_)
#define EMAX_  S3_
#define HID_   256
#define NFMAX_ (4*FN_)
#define PEMAX_ ((S3_/5)+64)
#define NEM_   (VN_ + PEMAX_ + 3*NFMAX_)
#define TPB    256
#define GS3    ((S3_ + TPB - 1)/TPB)
#define GF     ((FN_ + TPB - 1)/TPB)
#define GNE    ((NEM_ + TPB - 1)/TPB)
#define GNF3   ((3*NFMAX_ + TPB - 1)/TPB)

// ---------------- static device scratch (no allocation allowed) ----------------
__device__ unsigned g_sk_in[S3_], g_sk_out[S3_], g_sv_in[S3_], g_sv_out[S3_];
__device__ int g_flag[S3_], g_rank[S3_], g_inv[S3_];
__device__ int g_ukeys[EMAX_], g_runstart[EMAX_+1];
__device__ int g_en0[EMAX_], g_en1[EMAX_];
__device__ float g_xe[EMAX_*3];
__device__ float g_rq[EMAX_*4];      // r0,r1,q0,q1 per edge
__device__ float g_y[EMAX_];
__device__ unsigned long long g_yk_in[S3_], g_yk_out[S3_];
__device__ int g_sel[S3_], g_pp[S3_];
__device__ int g_flag8[8*FN_], g_pos8[8*FN_];
__device__ int g_nf[3*NFMAX_];
__device__ int g_E, g_num, g_T0, g_C1, g_C2, g_T7;
__device__ int g_NF, g_NE, g_oF, g_oNE, g_oM;
__device__ unsigned char g_temp[48u<<20];

// ---------------- threefry2x32, key = (0,42), JAX-exact ----------------
__device__ __forceinline__ unsigned rotl32(unsigned v, int d) {
    return (v << d) | (v >> (32 - d));
}
__device__ __forceinline__ void threefry_0_42(unsigned x0, unsigned x1,
                                              unsigned& o0, unsigned& o1) {
    const unsigned k0 = 0u, k1 = 42u;
    const unsigned ks2 = k0 ^ k1 ^ 0x1BD11BDAu;
    x0 += k0; x1 += k1;
#define TF4(a,b,c,d) \
    x0 += x1; x1 = rotl32(x1,a); x1 ^= x0; \
    x0 += x1; x1 = rotl32(x1,b); x1 ^= x0; \
    x0 += x1; x1 = rotl32(x1,c); x1 ^= x0; \
    x0 += x1; x1 = rotl32(x1,d); x1 ^= x0;
    TF4(13,15,26,6);   x0 += k1;  x1 += ks2 + 1u;
    TF4(17,29,16,24);  x0 += ks2; x1 += k0  + 2u;
    TF4(13,15,26,6);   x0 += k0;  x1 += k1  + 3u;
    TF4(17,29,16,24);  x0 += k1;  x1 += ks2 + 4u;
    TF4(13,15,26,6);   x0 += ks2; x1 += k0  + 5u;
#undef TF4
    o0 = x0; o1 = x1;
}
// Partitionable-threefry random bits (JAX >= 0.5 default):
// bits32[i] = o0 ^ o1 where (o0,o1) = threefry(key, (hi32(i), lo32(i))) = threefry((0,42),(0,i))
__device__ __forceinline__ unsigned tf_bits_part(unsigned i) {
    unsigned o0, o1;
    threefry_0_42(0u, i, o0, o1);
    return o0 ^ o1;
}

// ---------------- kernels ----------------
__global__ void k_build_keys(const int* __restrict__ face) {
    int i = blockIdx.x * blockDim.x + threadIdx.x;
    if (i >= S3_) return;
    int blk = i / FN_, fc = i - blk * FN_;
    int a, b;
    if (blk == 0)      { a = face[fc*3+0]; b = face[fc*3+1]; }
    else if (blk == 1) { a = face[fc*3+1]; b = face[fc*3+2]; }
    else               { a = face[fc*3+2]; b = face[fc*3+0]; }
    int lo = min(a, b), hi = max(a, b);
    int key = (int)((unsigned)lo * (unsigned)VN_ + (unsigned)hi); // int32 wrap like JAX
    g_sk_in[i] = (unsigned)key ^ 0x80000000u;  // signed order under unsigned radix
    g_sv_in[i] = (unsigned)i;
}

__global__ void k_head() {
    int i = blockIdx.x * blockDim.x + threadIdx.x;
    if (i >= S3_) return;
    g_flag[i] = (i == 0 || g_sk_out[i] != g_sk_out[i-1]) ? 1 : 0;
}

__global__ void k_unique() {
    int i = blockIdx.x * blockDim.x + threadIdx.x;
    if (i >= S3_) return;
    int r = g_rank[i];                 // inclusive scan of flags
    if (g_flag[i]) {
        g_ukeys[r-1]    = (int)(g_sk_out[i] ^ 0x80000000u);
        g_runstart[r-1] = i;
    }
    g_inv[g_sv_out[i]] = r - 1;
    if (i == S3_ - 1) { g_E = r; g_runstart[r] = S3_; }
}

__global__ void k_scalars(const int* __restrict__ divp) {
    if (threadIdx.x == 0 && blockIdx.x == 0) g_num = g_E / divp[0];
}

__global__ void k_edgenode_xe(const float* __restrict__ x) {
    int e = blockIdx.x * blockDim.x + threadIdx.x;
    if (e >= EMAX_ || e >= g_E) return;
    int k = g_ukeys[e];
    int q = k / VN_, r = k % VN_;      // C trunc -> numpy floor fixup
    if (r < 0) { r += VN_; q -= 1; }
    g_en0[e] = q; g_en1[e] = r;
    int i0 = (q < 0) ? q + VN_ : q;    // JAX gather: negative wrap, then clamp
    if (i0 < 0) i0 = 0;
    if (i0 >= VN_) i0 = VN_ - 1;
    #pragma unroll
    for (int c = 0; c < 3; c++)
        g_xe[e*3+c] = 0.5f * (x[i0*3+c] + x[r*3+c]);
}

__global__ void k_gnn1(const float* __restrict__ W1s, const float* __restrict__ W1n,
                       const float* __restrict__ b1,  const float* __restrict__ W2s,
                       const float* __restrict__ W2n) {
    __shared__ float s1s[3*HID_], s1n[3*HID_], sb[HID_], s2s[2*HID_], s2n[2*HID_];
    for (int i = threadIdx.x; i < 3*HID_; i += blockDim.x) { s1s[i] = W1s[i]; s1n[i] = W1n[i]; }
    for (int i = threadIdx.x; i < HID_;   i += blockDim.x) {
        sb[i] = b1[i];
        s2s[i] = W2s[i*2+0]; s2s[HID_+i] = W2s[i*2+1];
        s2n[i] = W2n[i*2+0]; s2n[HID_+i] = W2n[i*2+1];
    }
    __syncthreads();
    int e = blockIdx.x * blockDim.x + threadIdx.x;
    if (e >= EMAX_ || e >= g_E) return;
    int s = g_runstart[e], t = g_runstart[e+1];
    float deg = (float)(2*(t-s) + 1);
    float xe0 = g_xe[e*3+0], xe1 = g_xe[e*3+1], xe2 = g_xe[e*3+2];
    float ax0 = xe0, ax1 = xe1, ax2 = xe2;   // self loop
    for (int i = s; i < t; i++) {
        int slot = (int)g_sv_out[i];
        int fc = slot % FN_, j = slot / FN_;
        int e1 = g_inv[((j+1)%3)*FN_ + fc];
        int e2 = g_inv[((j+2)%3)*FN_ + fc];
        ax0 += g_xe[e1*3+0] + g_xe[e2*3+0];
        ax1 += g_xe[e1*3+1] + g_xe[e2*3+1];
        ax2 += g_xe[e1*3+2] + g_xe[e2*3+2];
    }
    ax0 /= deg; ax1 /= deg; ax2 /= deg;
    float r0 = 0.f, r1 = 0.f, q0 = 0.f, q1 = 0.f;
    #pragma unroll 4
    for (int k = 0; k < HID_; k++) {
        float pre = sb[k] + xe0*s1s[k] + xe1*s1s[HID_+k] + xe2*s1s[2*HID_+k]
                          + ax0*s1n[k] + ax1*s1n[HID_+k] + ax2*s1n[2*HID_+k];
        float h = fmaxf(pre, 0.f);
        r0 += h * s2s[k];  r1 += h * s2s[HID_+k];
        q0 += h * s2n[k];  q1 += h * s2n[HID_+k];
    }
    g_rq[e*4+0] = r0; g_rq[e*4+1] = r1; g_rq[e*4+2] = q0; g_rq[e*4+3] = q1;
}

__global__ void k_gumbel(const float* __restrict__ b2) {
    int e = blockIdx.x * blockDim.x + threadIdx.x;
    if (e >= S3_) return;
    int E = g_E;
    if (e >= E) {  // padding: sorts to the end (max 51-bit key)
        g_yk_in[e] = (((unsigned long long)0xFFFFFFFFu) << 19) | 0x7FFFFull;
        return;
    }
    int s = g_runstart[e], t = g_runstart[e+1];
    float deg = (float)(2*(t-s) + 1);
    float aq0 = g_rq[e*4+2], aq1 = g_rq[e*4+3];  // self loop
    for (int i = s; i < t; i++) {
        int slot = (int)g_sv_out[i];
        int fc = slot % FN_, j = slot / FN_;
        int e1 = g_inv[((j+1)%3)*FN_ + fc];
        int e2 = g_inv[((j+2)%3)*FN_ + fc];
        aq0 += g_rq[e1*4+2] + g_rq[e2*4+2];
        aq1 += g_rq[e1*4+3] + g_rq[e2*4+3];
    }
    float o0 = g_rq[e*4+0] + aq0/deg + b2[0];
    float o1 = g_rq[e*4+1] + aq1/deg + b2[1];
    float l0 = 1.f / (1.f + expf(-o0));           // sigmoid logits
    float l1 = 1.f / (1.f + expf(-o1));
    unsigned bb0 = tf_bits_part(2u*(unsigned)e);
    unsigned bb1 = tf_bits_part(2u*(unsigned)e + 1u);
    float U0 = __uint_as_float((bb0 >> 9) | 0x3F800000u) - 1.0f;
    float U1 = __uint_as_float((bb1 >> 9) | 0x3F800000u) - 1.0f;
    float gg0 = -logf(-logf(U0 + 1e-20f) + 1e-20f);
    float gg1 = -logf(-logf(U1 + 1e-20f) + 1e-20f);
    float z0 = (l0 + gg0) / 0.1f, z1 = (l1 + gg1) / 0.1f;
    float m  = fmaxf(z0, z1);
    float ez0 = expf(z0 - m), ez1 = expf(z1 - m);
    float y = ez0 / (ez0 + ez1);
    g_y[e] = y;
    unsigned fb = __float_as_uint(y);             // y >= 0
    unsigned hi = ~fb;                            // ascending u64 => descending y
    g_yk_in[e] = (((unsigned long long)hi) << 19) | (unsigned)e;  // tie-break: idx asc
}

__global__ void k_mark() {
    int r = blockIdx.x * blockDim.x + threadIdx.x;
    if (r >= S3_ || r >= g_num) return;
    unsigned idx = (unsigned)(g_yk_out[r] & 0x7FFFFull);
    g_sel[idx] = 1;
}

__global__ void k_cat() {
    int fc = blockIdx.x * blockDim.x + threadIdx.x;
    if (fc >= FN_) return;
    int m0 = g_sel[g_inv[fc]];
    int m1 = g_sel[g_inv[FN_ + fc]];
    int m2 = g_sel[g_inv[2*FN_ + fc]];
    int pen = m0 + m1 + m2;
    int psi = m1 + 2*m2;
    int cat = (pen == 0) ? 0 : (pen == 1) ? 1 + psi : (pen == 2) ? 3 + psi : 7;
    #pragma unroll
    for (int k = 0; k < 8; k++) g_flag8[k*FN_ + fc] = (k == cat) ? 1 : 0;
}

__global__ void k_finalize() {
    if (threadIdx.x || blockIdx.x) return;
    int P1 = g_pos8[FN_];      // = T0
    int P4 = g_pos8[4*FN_];    // = T0 + C1
    int P7 = g_pos8[7*FN_];    // = T0 + C1 + C2
    int T0 = P1, C1 = P4 - P1, C2 = P7 - P4, T7 = FN_ - P7;
    g_T0 = T0; g_C1 = C1; g_C2 = C2; g_T7 = T7;
    int NF = T0 + 2*C1 + 3*C2 + 4*T7;
    g_NF = NF;
    g_NE = VN_ + g_num + 3*NF;
    g_oF  = 2*g_E;
    g_oNE = g_oF + 3*NF;
    g_oM  = g_oNE + 2*g_NE;
}

__device__ __forceinline__ void wtri(int row, int a, int b, int c) {
    g_nf[row*3+0] = a; g_nf[row*3+1] = b; g_nf[row*3+2] = c;
}

__global__ void k_faces(const int* __restrict__ face) {
    int fc = blockIdx.x * blockDim.x + threadIdx.x;
    if (fc >= FN_) return;
    int f0 = face[fc*3+0], f1 = face[fc*3+1], f2 = face[fc*3+2];
    int e0 = g_inv[fc], e1 = g_inv[FN_+fc], e2 = g_inv[2*FN_+fc];
    int m0 = g_sel[e0], m1 = g_sel[e1], m2 = g_sel[e2];
    int p0 = VN_ + g_pp[e0], p1 = VN_ + g_pp[e1], p2 = VN_ + g_pp[e2];
    int pen = m0 + m1 + m2, psi = m1 + 2*m2;
    int cat = (pen == 0) ? 0 : (pen == 1) ? 1 + psi : (pen == 2) ? 3 + psi : 7;
    int pos = g_pos8[cat*FN_ + fc];
    int T0 = g_T0, C1 = g_C1, C2 = g_C2, T7 = g_T7;
    if (cat == 0) {
        wtri(pos, f0, f1, f2);
    } else if (cat <= 3) {                  // pen==1, psi = cat-1
        int g = pos - T0;
        int rA = T0 + g, rB = T0 + C1 + g;
        if (cat == 1)      { wtri(rA, f0, p0, f2); wtri(rB, p0, f1, f2); }
        else if (cat == 2) { wtri(rA, f1, p1, f0); wtri(rB, p1, f2, f0); }
        else               { wtri(rA, f2, p2, f1); wtri(rB, p2, f0, f1); }
    } else if (cat <= 6) {                  // pen==2, psi = cat-3
        int g = pos - (T0 + C1);
        int base2 = T0 + 2*C1;
        int rA = base2 + g, rB = base2 + C2 + g, rC = base2 + 2*C2 + g;
        if (cat == 4)      { wtri(rA, f0, p0, f2); wtri(rB, p0, f1, p1); wtri(rC, p0, p1, f2); }
        else if (cat == 5) { wtri(rA, f2, p2, f1); wtri(rB, p2, f0, p0); wtri(rC, p2, p0, f1); }
        else               { wtri(rA, f1, p1, f0); wtri(rB, p1, f2, p2); wtri(rC, p1, p2, f0); }
    } else {                                // pen==3
        int r = pos - (T0 + C1 + C2);
        int base3 = T0 + 2*C1 + 3*C2;
        wtri(base3 + r,        f0, p0, p2);
        wtri(base3 + T7 + r,   p0, f1, p1);
        wtri(base3 + 2*T7 + r, p0, p1, p2);
        wtri(base3 + 3*T7 + r, p1, f2, p2);
    }
}

__global__ void k_out_en(float* __restrict__ out) {
    int e = blockIdx.x * blockDim.x + threadIdx.x;
    if (e >= EMAX_ || e >= g_E) return;
    out[2*e]   = (float)g_en0[e];
    out[2*e+1] = (float)g_en1[e];
    float y  = g_y[e];
    float yh = g_sel[e] ? 1.f : 0.f;
    out[g_oM + e] = (yh - y) + y;      // straight-through mask, fp-exact formula
}

__global__ void k_out_faces(float* __restrict__ out) {
    int i = blockIdx.x * blockDim.x + threadIdx.x;
    if (i >= 3*NFMAX_ || i >= 3*g_NF) return;
    out[g_oF + i] = (float)g_nf[i];
}

__global__ void k_out_edges(float* __restrict__ out) {
    int t = blockIdx.x * blockDim.x + threadIdx.x;
    if (t >= NEM_ || t >= g_NE) return;
    int NF = g_NF, base = VN_ + g_num;
    int s, d;
    if (t < base) { s = t; d = t; }
    else {
        int u = t - base;
        if (u < NF)          { s = g_nf[u*3+0];        d = g_nf[u*3+1]; }
        else if (u < 2*NF)   { int r = u - NF;   s = g_nf[r*3+1]; d = g_nf[r*3+2]; }
        else                 { int r = u - 2*NF; s = g_nf[r*3+2]; d = g_nf[r*3+0]; }
    }
    out[g_oNE + t]        = (float)s;
    out[g_oNE + g_NE + t] = (float)d;
}

// ---------------- host ----------------
extern "C" void kernel_launch(void* const* d_in, const int* in_sizes, int n_in,
                              void* d_out, int out_size) {
    const float* x    = (const float*)d_in[0];
    const int*   face = (const int*)d_in[1];
    const int*   divp = (const int*)d_in[4];
    const float* W1s  = (const float*)d_in[5];
    const float* W1n  = (const float*)d_in[6];
    const float* b1   = (const float*)d_in[7];
    const float* W2s  = (const float*)d_in[8];
    const float* W2n  = (const float*)d_in[9];
    const float* b2   = (const float*)d_in[10];
    float* out = (float*)d_out;

    void *tp, *psk_in, *psk_out, *psv_in, *psv_out, *pflag, *prank;
    void *pyk_in, *pyk_out, *psel, *ppp, *pflag8, *ppos8;
    cudaGetSymbolAddress(&tp,      g_temp);
    cudaGetSymbolAddress(&psk_in,  g_sk_in);
    cudaGetSymbolAddress(&psk_out, g_sk_out);
    cudaGetSymbolAddress(&psv_in,  g_sv_in);
    cudaGetSymbolAddress(&psv_out, g_sv_out);
    cudaGetSymbolAddress(&pflag,   g_flag);
    cudaGetSymbolAddress(&prank,   g_rank);
    cudaGetSymbolAddress(&pyk_in,  g_yk_in);
    cudaGetSymbolAddress(&pyk_out, g_yk_out);
    cudaGetSymbolAddress(&psel,    g_sel);
    cudaGetSymbolAddress(&ppp,     g_pp);
    cudaGetSymbolAddress(&pflag8,  g_flag8);
    cudaGetSymbolAddress(&ppos8,   g_pos8);
    cudaStream_t st = 0;
    size_t tb;

    k_build_keys<<<GS3, TPB, 0, st>>>(face);

    tb = sizeof(g_temp);
    cub::DeviceRadixSort::SortPairs(tp, tb,
        (const unsigned*)psk_in, (unsigned*)psk_out,
        (const unsigned*)psv_in, (unsigned*)psv_out, S3_, 0, 32, st);

    k_head<<<GS3, TPB, 0, st>>>();
    tb = sizeof(g_temp);
    cub::DeviceScan::InclusiveSum(tp, tb, (const int*)pflag, (int*)prank, S3_, st);
    k_unique<<<GS3, TPB, 0, st>>>();
    k_scalars<<<1, 1, 0, st>>>(divp);
    k_edgenode_xe<<<GS3, TPB, 0, st>>>(x);
    k_gnn1<<<GS3, TPB, 0, st>>>(W1s, W1n, b1, W2s, W2n);
    k_gumbel<<<GS3, TPB, 0, st>>>(b2);

    tb = sizeof(g_temp);
    cub::DeviceRadixSort::SortKeys(tp, tb,
        (const unsigned long long*)pyk_in, (unsigned long long*)pyk_out,
        S3_, 0, 51, st);

    cudaMemsetAsync(psel, 0, S3_ * sizeof(int), st);
    k_mark<<<GS3, TPB, 0, st>>>();
    tb = sizeof(g_temp);
    cub::DeviceScan::ExclusiveSum(tp, tb, (const int*)psel, (int*)ppp, S3_, st);
    k_cat<<<GF, TPB, 0, st>>>();
    tb = sizeof(g_temp);
    cub::DeviceScan::ExclusiveSum(tp, tb, (const int*)pflag8, (int*)ppos8, 8*FN_, st);
    k_finalize<<<1, 1, 0, st>>>();
    k_faces<<<GF, TPB, 0, st>>>(face);

    k_out_en<<<GS3, TPB, 0, st>>>(out);
    k_out_faces<<<GNF3, TPB, 0, st>>>(out);
    k_out_edges<<<GNE, TPB, 0, st>>>(out);
}

// round 5
// speedup vs baseline: 1.1534x; 1.1534x over previous
#include <cuda_runtime.h>
#include <cstdint>
#include <cub/cub.cuh>

#define VN_    50000
#define FN_    100000
#define S3_    (3*FN_)
#define EMAX_  S3_
#define HID_   256
#define NFMAX_ (4*FN_)
#define PEMAX_ ((S3_/5)+64)
#define NEM_   (VN_ + PEMAX_ + 3*NFMAX_)
#define SF_    (S3_ + 8*FN_)          // combined sel+flag8 scan length
#define TPB    256
#define GS3    ((S3_ + TPB - 1)/TPB)
#define GF     ((FN_ + TPB - 1)/TPB)
#define GNE    ((NEM_ + TPB - 1)/TPB)
#define GNF3   ((3*NFMAX_ + TPB - 1)/TPB)

// ---------------- static device scratch (no allocation allowed) ----------------
__device__ unsigned g_sk_in[S3_], g_sk_out[S3_], g_sv_in[S3_], g_sv_out[S3_];
__device__ int g_flag[S3_], g_rank[S3_], g_inv[S3_];
__device__ int g_runstart[EMAX_+1];
__device__ int g_en0[EMAX_], g_en1[EMAX_];
__device__ float g_xe[EMAX_*3];
__device__ float g_rq[EMAX_*4];      // r0,r1,q0,q1 per edge
__device__ float g_y[EMAX_];
__device__ unsigned g_yk_in[S3_], g_yk_out[S3_], g_yv_in[S3_], g_yv_out[S3_];
__device__ int g_selflag[SF_];       // [0,S3_): sel ; [S3_,S3_+8FN): flag8
__device__ int g_scan[SF_];          // exclusive scan of g_selflag
__device__ int g_nf[3*NFMAX_];
__device__ int g_E, g_num;
__device__ unsigned char g_temp[48u<<20];

// ---------------- threefry2x32, key = (0,42), JAX-exact ----------------
__device__ __forceinline__ unsigned rotl32(unsigned v, int d) {
    return (v << d) | (v >> (32 - d));
}
__device__ __forceinline__ void threefry_0_42(unsigned x0, unsigned x1,
                                              unsigned& o0, unsigned& o1) {
    const unsigned k0 = 0u, k1 = 42u;
    const unsigned ks2 = k0 ^ k1 ^ 0x1BD11BDAu;
    x0 += k0; x1 += k1;
#define TF4(a,b,c,d) \
    x0 += x1; x1 = rotl32(x1,a); x1 ^= x0; \
    x0 += x1; x1 = rotl32(x1,b); x1 ^= x0; \
    x0 += x1; x1 = rotl32(x1,c); x1 ^= x0; \
    x0 += x1; x1 = rotl32(x1,d); x1 ^= x0;
    TF4(13,15,26,6);   x0 += k1;  x1 += ks2 + 1u;
    TF4(17,29,16,24);  x0 += ks2; x1 += k0  + 2u;
    TF4(13,15,26,6);   x0 += k0;  x1 += k1  + 3u;
    TF4(17,29,16,24);  x0 += k1;  x1 += ks2 + 4u;
    TF4(13,15,26,6);   x0 += ks2; x1 += k0  + 5u;
#undef TF4
    o0 = x0; o1 = x1;
}
// Partitionable-threefry random bits (JAX >= 0.5 default):
// bits32[i] = o0 ^ o1 with (o0,o1) = threefry((0,42), (0, i))
__device__ __forceinline__ unsigned tf_bits_part(unsigned i) {
    unsigned o0, o1;
    threefry_0_42(0u, i, o0, o1);
    return o0 ^ o1;
}

// derived category counts from the combined scan (cheap, L2-broadcast loads)
__device__ __forceinline__ void cat_counts(int& T0, int& C1, int& C2, int& T7) {
    int num = g_num;
    int P1 = g_scan[S3_ +   FN_] - num;
    int P4 = g_scan[S3_ + 4*FN_] - num;
    int P7 = g_scan[S3_ + 7*FN_] - num;
    T0 = P1; C1 = P4 - P1; C2 = P7 - P4; T7 = FN_ - P7;
}
__device__ __forceinline__ int nf_total() {
    int T0, C1, C2, T7; cat_counts(T0, C1, C2, T7);
    return T0 + 2*C1 + 3*C2 + 4*T7;
}

// ---------------- kernels ----------------
__global__ void k_build_keys(const int* __restrict__ face) {
    int i = blockIdx.x * blockDim.x + threadIdx.x;
    if (i >= S3_) return;
    int blk = i / FN_, fc = i - blk * FN_;
    int a, b;
    if (blk == 0)      { a = face[fc*3+0]; b = face[fc*3+1]; }
    else if (blk == 1) { a = face[fc*3+1]; b = face[fc*3+2]; }
    else               { a = face[fc*3+2]; b = face[fc*3+0]; }
    int lo = min(a, b), hi = max(a, b);
    int key = (int)((unsigned)lo * (unsigned)VN_ + (unsigned)hi); // int32 wrap like JAX
    g_sk_in[i] = (unsigned)key ^ 0x80000000u;  // signed order under unsigned radix
    g_sv_in[i] = (unsigned)i;
}

__global__ void k_head() {
    int i = blockIdx.x * blockDim.x + threadIdx.x;
    if (i >= S3_) return;
    g_flag[i] = (i == 0 || g_sk_out[i] != g_sk_out[i-1]) ? 1 : 0;
}

// unique + inverse map + scalars + edge-node endpoints + xe, all fused
__global__ void k_unique(const float* __restrict__ x, const int* __restrict__ divp) {
    int i = blockIdx.x * blockDim.x + threadIdx.x;
    if (i >= S3_) return;
    int r = g_rank[i];                 // inclusive scan of flags
    if (g_flag[i]) {
        int e = r - 1;
        g_runstart[e] = i;
        int k = (int)(g_sk_out[i] ^ 0x80000000u);
        int q = k / VN_, rm = k % VN_;     // C trunc -> numpy floor fixup
        if (rm < 0) { rm += VN_; q -= 1; }
        g_en0[e] = q; g_en1[e] = rm;
        int i0 = (q < 0) ? q + VN_ : q;    // JAX gather: negative wrap, then clamp
        if (i0 < 0) i0 = 0;
        if (i0 >= VN_) i0 = VN_ - 1;
        #pragma unroll
        for (int c = 0; c < 3; c++)
            g_xe[e*3+c] = 0.5f * (x[i0*3+c] + x[rm*3+c]);
    }
    g_inv[g_sv_out[i]] = r - 1;
    if (i == S3_ - 1) { g_E = r; g_runstart[r] = S3_; g_num = r / divp[0]; }
}

__global__ void k_gnn1(const float* __restrict__ W1s, const float* __restrict__ W1n,
                       const float* __restrict__ b1,  const float* __restrict__ W2s,
                       const float* __restrict__ W2n) {
    __shared__ float s1s[3*HID_], s1n[3*HID_], sb[HID_], s2s[2*HID_], s2n[2*HID_];
    for (int i = threadIdx.x; i < 3*HID_; i += blockDim.x) { s1s[i] = W1s[i]; s1n[i] = W1n[i]; }
    for (int i = threadIdx.x; i < HID_;   i += blockDim.x) {
        sb[i] = b1[i];
        s2s[i] = W2s[i*2+0]; s2s[HID_+i] = W2s[i*2+1];
        s2n[i] = W2n[i*2+0]; s2n[HID_+i] = W2n[i*2+1];
    }
    __syncthreads();
    int e = blockIdx.x * blockDim.x + threadIdx.x;
    if (e >= EMAX_ || e >= g_E) return;
    int s = g_runstart[e], t = g_runstart[e+1];
    float deg = (float)(2*(t-s) + 1);
    float xe0 = g_xe[e*3+0], xe1 = g_xe[e*3+1], xe2 = g_xe[e*3+2];
    float ax0 = xe0, ax1 = xe1, ax2 = xe2;   // self loop
    for (int i = s; i < t; i++) {
        int slot = (int)g_sv_out[i];
        int fc = slot % FN_, j = slot / FN_;
        int e1 = g_inv[((j+1)%3)*FN_ + fc];
        int e2 = g_inv[((j+2)%3)*FN_ + fc];
        ax0 += g_xe[e1*3+0] + g_xe[e2*3+0];
        ax1 += g_xe[e1*3+1] + g_xe[e2*3+1];
        ax2 += g_xe[e1*3+2] + g_xe[e2*3+2];
    }
    ax0 /= deg; ax1 /= deg; ax2 /= deg;
    float r0 = 0.f, r1 = 0.f, q0 = 0.f, q1 = 0.f;
    #pragma unroll 4
    for (int k = 0; k < HID_; k++) {
        float pre = sb[k] + xe0*s1s[k] + xe1*s1s[HID_+k] + xe2*s1s[2*HID_+k]
                          + ax0*s1n[k] + ax1*s1n[HID_+k] + ax2*s1n[2*HID_+k];
        float h = fmaxf(pre, 0.f);
        r0 += h * s2s[k];  r1 += h * s2s[HID_+k];
        q0 += h * s2n[k];  q1 += h * s2n[HID_+k];
    }
    g_rq[e*4+0] = r0; g_rq[e*4+1] = r1; g_rq[e*4+2] = q0; g_rq[e*4+3] = q1;
}

__global__ void k_gumbel(const float* __restrict__ b2) {
    int e = blockIdx.x * blockDim.x + threadIdx.x;
    if (e >= S3_) return;
    g_selflag[e] = 0;                   // zero sel (replaces memset node)
    int E = g_E;
    g_yv_in[e] = (unsigned)e;
    if (e >= E) {                       // padding: max key; stability keeps real first
        g_yk_in[e] = 0x3FFFFFFFu;
        return;
    }
    int s = g_runstart[e], t = g_runstart[e+1];
    float deg = (float)(2*(t-s) + 1);
    float aq0 = g_rq[e*4+2], aq1 = g_rq[e*4+3];  // self loop
    for (int i = s; i < t; i++) {
        int slot = (int)g_sv_out[i];
        int fc = slot % FN_, j = slot / FN_;
        int e1 = g_inv[((j+1)%3)*FN_ + fc];
        int e2 = g_inv[((j+2)%3)*FN_ + fc];
        aq0 += g_rq[e1*4+2] + g_rq[e2*4+2];
        aq1 += g_rq[e1*4+3] + g_rq[e2*4+3];
    }
    float o0 = g_rq[e*4+0] + aq0/deg + b2[0];
    float o1 = g_rq[e*4+1] + aq1/deg + b2[1];
    float l0 = 1.f / (1.f + expf(-o0));           // sigmoid logits
    float l1 = 1.f / (1.f + expf(-o1));
    unsigned bb0 = tf_bits_part(2u*(unsigned)e);
    unsigned bb1 = tf_bits_part(2u*(unsigned)e + 1u);
    float U0 = __uint_as_float((bb0 >> 9) | 0x3F800000u) - 1.0f;
    float U1 = __uint_as_float((bb1 >> 9) | 0x3F800000u) - 1.0f;
    float gg0 = -logf(-logf(U0 + 1e-20f) + 1e-20f);
    float gg1 = -logf(-logf(U1 + 1e-20f) + 1e-20f);
    float z0 = (l0 + gg0) / 0.1f, z1 = (l1 + gg1) / 0.1f;
    float m  = fmaxf(z0, z1);
    float ez0 = expf(z0 - m), ez1 = expf(z1 - m);
    float y = ez0 / (ez0 + ez1);
    g_y[e] = y;
    // y in [0,1] => float bits <= 0x3F800000 (30 bits). Descending y == ascending ~bits.
    // Radix sort is STABLE => ascending-index tie-break matches lax.top_k exactly.
    g_yk_in[e] = (~__float_as_uint(y)) & 0x3FFFFFFFu;
}

__global__ void k_mark() {
    int r = blockIdx.x * blockDim.x + threadIdx.x;
    if (r >= S3_ || r >= g_num) return;
    g_selflag[g_yv_out[r]] = 1;
}

__global__ void k_cat() {
    int fc = blockIdx.x * blockDim.x + threadIdx.x;
    if (fc >= FN_) return;
    int m0 = g_selflag[g_inv[fc]];
    int m1 = g_selflag[g_inv[FN_ + fc]];
    int m2 = g_selflag[g_inv[2*FN_ + fc]];
    int pen = m0 + m1 + m2;
    int psi = m1 + 2*m2;
    int cat = (pen == 0) ? 0 : (pen == 1) ? 1 + psi : (pen == 2) ? 3 + psi : 7;
    #pragma unroll
    for (int k = 0; k < 8; k++) g_selflag[S3_ + k*FN_ + fc] = (k == cat) ? 1 : 0;
}

__device__ __forceinline__ void wtri(int row, int a, int b, int c) {
    g_nf[row*3+0] = a; g_nf[row*3+1] = b; g_nf[row*3+2] = c;
}

__global__ void k_faces(const int* __restrict__ face) {
    int fc = blockIdx.x * blockDim.x + threadIdx.x;
    if (fc >= FN_) return;
    int T0, C1, C2, T7; cat_counts(T0, C1, C2, T7);
    int num = g_num;
    int f0 = face[fc*3+0], f1 = face[fc*3+1], f2 = face[fc*3+2];
    int e0 = g_inv[fc], e1 = g_inv[FN_+fc], e2 = g_inv[2*FN_+fc];
    int m0 = g_selflag[e0], m1 = g_selflag[e1], m2 = g_selflag[e2];
    int p0 = VN_ + g_scan[e0], p1 = VN_ + g_scan[e1], p2 = VN_ + g_scan[e2];
    int pen = m0 + m1 + m2, psi = m1 + 2*m2;
    int cat = (pen == 0) ? 0 : (pen == 1) ? 1 + psi : (pen == 2) ? 3 + psi : 7;
    int pos = g_scan[S3_ + cat*FN_ + fc] - num;
    if (cat == 0) {
        wtri(pos, f0, f1, f2);
    } else if (cat <= 3) {                  // pen==1, psi = cat-1
        int g = pos - T0;
        int rA = T0 + g, rB = T0 + C1 + g;
        if (cat == 1)      { wtri(rA, f0, p0, f2); wtri(rB, p0, f1, f2); }
        else if (cat == 2) { wtri(rA, f1, p1, f0); wtri(rB, p1, f2, f0); }
        else               { wtri(rA, f2, p2, f1); wtri(rB, p2, f0, f1); }
    } else if (cat <= 6) {                  // pen==2, psi = cat-3
        int g = pos - (T0 + C1);
        int base2 = T0 + 2*C1;
        int rA = base2 + g, rB = base2 + C2 + g, rC = base2 + 2*C2 + g;
        if (cat == 4)      { wtri(rA, f0, p0, f2); wtri(rB, p0, f1, p1); wtri(rC, p0, p1, f2); }
        else if (cat == 5) { wtri(rA, f2, p2, f1); wtri(rB, p2, f0, p0); wtri(rC, p2, p0, f1); }
        else               { wtri(rA, f1, p1, f0); wtri(rB, p1, f2, p2); wtri(rC, p1, p2, f0); }
    } else {                                // pen==3
        int r = pos - (T0 + C1 + C2);
        int base3 = T0 + 2*C1 + 3*C2;
        wtri(base3 + r,        f0, p0, p2);
        wtri(base3 + T7 + r,   p0, f1, p1);
        wtri(base3 + 2*T7 + r, p0, p1, p2);
        wtri(base3 + 3*T7 + r, p1, f2, p2);
    }
}

__global__ void k_out_en(float* __restrict__ out) {
    int e = blockIdx.x * blockDim.x + threadIdx.x;
    if (e >= EMAX_ || e >= g_E) return;
    int NF = nf_total();
    int NE = VN_ + g_num + 3*NF;
    int oM = 2*g_E + 3*NF + 2*NE;
    out[2*e]   = (float)g_en0[e];
    out[2*e+1] = (float)g_en1[e];
    float y  = g_y[e];
    float yh = g_selflag[e] ? 1.f : 0.f;
    out[oM + e] = (yh - y) + y;      // straight-through mask, fp-exact formula
}

__global__ void k_out_faces(float* __restrict__ out) {
    int i = blockIdx.x * blockDim.x + threadIdx.x;
    if (i >= 3*NFMAX_) return;
    if (i >= 3*nf_total()) return;
    out[2*g_E + i] = (float)g_nf[i];
}

__global__ void k_out_edges(float* __restrict__ out) {
    int t = blockIdx.x * blockDim.x + threadIdx.x;
    if (t >= NEM_) return;
    int NF = nf_total();
    int NE = VN_ + g_num + 3*NF;
    if (t >= NE) return;
    int oNE = 2*g_E + 3*NF;
    int base = VN_ + g_num;
    int s, d;
    if (t < base) { s = t; d = t; }
    else {
        int u = t - base;
        if (u < NF)          { s = g_nf[u*3+0];        d = g_nf[u*3+1]; }
        else if (u < 2*NF)   { int r = u - NF;   s = g_nf[r*3+1]; d = g_nf[r*3+2]; }
        else                 { int r = u - 2*NF; s = g_nf[r*3+2]; d = g_nf[r*3+0]; }
    }
    out[oNE + t]      = (float)s;
    out[oNE + NE + t] = (float)d;
}

// ---------------- host ----------------
extern "C" void kernel_launch(void* const* d_in, const int* in_sizes, int n_in,
                              void* d_out, int out_size) {
    const float* x    = (const float*)d_in[0];
    const int*   face = (const int*)d_in[1];
    const int*   divp = (const int*)d_in[4];
    const float* W1s  = (const float*)d_in[5];
    const float* W1n  = (const float*)d_in[6];
    const float* b1   = (const float*)d_in[7];
    const float* W2s  = (const float*)d_in[8];
    const float* W2n  = (const float*)d_in[9];
    const float* b2   = (const float*)d_in[10];
    float* out = (float*)d_out;

    void *tp, *psk_in, *psk_out, *psv_in, *psv_out, *pflag, *prank;
    void *pyk_in, *pyk_out, *pyv_in, *pyv_out, *pselflag, *pscan;
    cudaGetSymbolAddress(&tp,      g_temp);
    cudaGetSymbolAddress(&psk_in,  g_sk_in);
    cudaGetSymbolAddress(&psk_out, g_sk_out);
    cudaGetSymbolAddress(&psv_in,  g_sv_in);
    cudaGetSymbolAddress(&psv_out, g_sv_out);
    cudaGetSymbolAddress(&pflag,   g_flag);
    cudaGetSymbolAddress(&prank,   g_rank);
    cudaGetSymbolAddress(&pyk_in,  g_yk_in);
    cudaGetSymbolAddress(&pyk_out, g_yk_out);
    cudaGetSymbolAddress(&pyv_in,  g_yv_in);
    cudaGetSymbolAddress(&pyv_out, g_yv_out);
    cudaGetSymbolAddress(&pselflag,g_selflag);
    cudaGetSymbolAddress(&pscan,   g_scan);
    cudaStream_t st = 0;
    size_t tb;

    k_build_keys<<<GS3, TPB, 0, st>>>(face);

    tb = sizeof(g_temp);
    cub::DeviceRadixSort::SortPairs(tp, tb,
        (const unsigned*)psk_in, (unsigned*)psk_out,
        (const unsigned*)psv_in, (unsigned*)psv_out, S3_, 0, 32, st);

    k_head<<<GS3, TPB, 0, st>>>();
    tb = sizeof(g_temp);
    cub::DeviceScan::InclusiveSum(tp, tb, (const int*)pflag, (int*)prank, S3_, st);
    k_unique<<<GS3, TPB, 0, st>>>(x, divp);
    k_gnn1<<<GS3, TPB, 0, st>>>(W1s, W1n, b1, W2s, W2n);
    k_gumbel<<<GS3, TPB, 0, st>>>(b2);

    // 30-bit stable pair sort replicates top_k's (y desc, idx asc) order
    tb = sizeof(g_temp);
    cub::DeviceRadixSort::SortPairs(tp, tb,
        (const unsigned*)pyk_in, (unsigned*)pyk_out,
        (const unsigned*)pyv_in, (unsigned*)pyv_out, S3_, 0, 30, st);

    k_mark<<<GS3, TPB, 0, st>>>();
    k_cat<<<GF, TPB, 0, st>>>();
    // one combined scan: sel (pool ranks) + 8-category face flags
    tb = sizeof(g_temp);
    cub::DeviceScan::ExclusiveSum(tp, tb, (const int*)pselflag, (int*)pscan, SF_, st);
    k_faces<<<GF, TPB, 0, st>>>(face);

    k_out_en<<<GS3, TPB, 0, st>>>(out);
    k_out_faces<<<GNF3, TPB, 0, st>>>(out);
    k_out_edges<<<GNE, TPB, 0, st>>>(out);
}

// round 6
// speedup vs baseline: 1.2312x; 1.0674x over previous
#include <cuda_runtime.h>
#include <cstdint>
#include <cub/cub.cuh>

#define VN_    50000
#define FN_    100000
#define S3_    (3*FN_)
#define EMAX_  S3_
#define HID_   256
#define NFMAX_ (4*FN_)
#define PEMAX_ ((S3_/5)+64)
#define NEM_   (VN_ + PEMAX_ + 3*NFMAX_)
#define SF_    (S3_ + 8*FN_)          // combined sel+flag8 scan length
#define TPB    256
#define GS3    ((S3_ + TPB - 1)/TPB)
#define GF     ((FN_ + TPB - 1)/TPB)
#define GNE    ((NEM_ + TPB - 1)/TPB)
#define GNF3   ((3*NFMAX_ + TPB - 1)/TPB)

// ---------------- static device scratch (no allocation allowed) ----------------
__device__ unsigned g_sk_in[S3_], g_sk_out[S3_], g_sv_in[S3_], g_sv_out[S3_];
__device__ int g_flag[S3_], g_rank[S3_], g_inv[S3_];
__device__ int g_runstart[EMAX_+1];
__device__ int g_en0[EMAX_], g_en1[EMAX_];
__device__ float g_xe[EMAX_*3];
__device__ float g_rq[EMAX_*4];      // r0,r1,q0,q1 per edge
__device__ float g_y[EMAX_];
__device__ unsigned g_yk[S3_];       // 30-bit selection keys (~float_bits(y))
__device__ int g_selflag[SF_];       // [0,S3_): sel ; [S3_,S3_+8FN): flag8
__device__ int g_scan[SF_];          // exclusive scan of g_selflag
__device__ int g_nf[3*NFMAX_];
__device__ int g_hist[256];          // radix-select histogram (zero on load; picks re-zero)
__device__ unsigned g_prefix;        // radix-select prefix / final threshold key T
__device__ int g_selR;               // remaining count within threshold bucket
__device__ int g_E, g_num;
__device__ unsigned char g_temp[48u<<20];

// ---------------- threefry2x32, key = (0,42), JAX-exact ----------------
__device__ __forceinline__ unsigned rotl32(unsigned v, int d) {
    return (v << d) | (v >> (32 - d));
}
__device__ __forceinline__ void threefry_0_42(unsigned x0, unsigned x1,
                                              unsigned& o0, unsigned& o1) {
    const unsigned k0 = 0u, k1 = 42u;
    const unsigned ks2 = k0 ^ k1 ^ 0x1BD11BDAu;
    x0 += k0; x1 += k1;
#define TF4(a,b,c,d) \
    x0 += x1; x1 = rotl32(x1,a); x1 ^= x0; \
    x0 += x1; x1 = rotl32(x1,b); x1 ^= x0; \
    x0 += x1; x1 = rotl32(x1,c); x1 ^= x0; \
    x0 += x1; x1 = rotl32(x1,d); x1 ^= x0;
    TF4(13,15,26,6);   x0 += k1;  x1 += ks2 + 1u;
    TF4(17,29,16,24);  x0 += ks2; x1 += k0  + 2u;
    TF4(13,15,26,6);   x0 += k0;  x1 += k1  + 3u;
    TF4(17,29,16,24);  x0 += k1;  x1 += ks2 + 4u;
    TF4(13,15,26,6);   x0 += ks2; x1 += k0  + 5u;
#undef TF4
    o0 = x0; o1 = x1;
}
// Partitionable-threefry random bits (JAX >= 0.5 default):
// bits32[i] = o0 ^ o1 with (o0,o1) = threefry((0,42), (0, i))
__device__ __forceinline__ unsigned tf_bits_part(unsigned i) {
    unsigned o0, o1;
    threefry_0_42(0u, i, o0, o1);
    return o0 ^ o1;
}

// derived category counts from the combined scan (cheap, L2-broadcast loads)
__device__ __forceinline__ void cat_counts(int& T0, int& C1, int& C2, int& T7) {
    int num = g_num;
    int P1 = g_scan[S3_ +   FN_] - num;
    int P4 = g_scan[S3_ + 4*FN_] - num;
    int P7 = g_scan[S3_ + 7*FN_] - num;
    T0 = P1; C1 = P4 - P1; C2 = P7 - P4; T7 = FN_ - P7;
}
__device__ __forceinline__ int nf_total() {
    int T0, C1, C2, T7; cat_counts(T0, C1, C2, T7);
    return T0 + 2*C1 + 3*C2 + 4*T7;
}

// ---------------- kernels ----------------
__global__ void k_build_keys(const int* __restrict__ face) {
    int i = blockIdx.x * blockDim.x + threadIdx.x;
    if (i >= S3_) return;
    int blk = i / FN_, fc = i - blk * FN_;
    int a, b;
    if (blk == 0)      { a = face[fc*3+0]; b = face[fc*3+1]; }
    else if (blk == 1) { a = face[fc*3+1]; b = face[fc*3+2]; }
    else               { a = face[fc*3+2]; b = face[fc*3+0]; }
    int lo = min(a, b), hi = max(a, b);
    int key = (int)((unsigned)lo * (unsigned)VN_ + (unsigned)hi); // int32 wrap like JAX
    g_sk_in[i] = (unsigned)key ^ 0x80000000u;  // signed order under unsigned radix
    g_sv_in[i] = (unsigned)i;
}

__global__ void k_head() {
    int i = blockIdx.x * blockDim.x + threadIdx.x;
    if (i >= S3_) return;
    g_flag[i] = (i == 0 || g_sk_out[i] != g_sk_out[i-1]) ? 1 : 0;
}

// unique + inverse map + scalars + edge-node endpoints + xe, all fused
__global__ void k_unique(const float* __restrict__ x, const int* __restrict__ divp) {
    int i = blockIdx.x * blockDim.x + threadIdx.x;
    if (i >= S3_) return;
    int r = g_rank[i];                 // inclusive scan of flags
    if (g_flag[i]) {
        int e = r - 1;
        g_runstart[e] = i;
        int k = (int)(g_sk_out[i] ^ 0x80000000u);
        int q = k / VN_, rm = k % VN_;     // C trunc -> numpy floor fixup
        if (rm < 0) { rm += VN_; q -= 1; }
        g_en0[e] = q; g_en1[e] = rm;
        int i0 = (q < 0) ? q + VN_ : q;    // JAX gather: negative wrap, then clamp
        if (i0 < 0) i0 = 0;
        if (i0 >= VN_) i0 = VN_ - 1;
        #pragma unroll
        for (int c = 0; c < 3; c++)
            g_xe[e*3+c] = 0.5f * (x[i0*3+c] + x[rm*3+c]);
    }
    g_inv[g_sv_out[i]] = r - 1;
    if (i == S3_ - 1) { g_E = r; g_runstart[r] = S3_; g_num = r / divp[0]; }
}

__global__ void k_gnn1(const float* __restrict__ W1s, const float* __restrict__ W1n,
                       const float* __restrict__ b1,  const float* __restrict__ W2s,
                       const float* __restrict__ W2n) {
    __shared__ float s1s[3*HID_], s1n[3*HID_], sb[HID_], s2s[2*HID_], s2n[2*HID_];
    for (int i = threadIdx.x; i < 3*HID_; i += blockDim.x) { s1s[i] = W1s[i]; s1n[i] = W1n[i]; }
    for (int i = threadIdx.x; i < HID_;   i += blockDim.x) {
        sb[i] = b1[i];
        s2s[i] = W2s[i*2+0]; s2s[HID_+i] = W2s[i*2+1];
        s2n[i] = W2n[i*2+0]; s2n[HID_+i] = W2n[i*2+1];
    }
    __syncthreads();
    int e = blockIdx.x * blockDim.x + threadIdx.x;
    if (e >= EMAX_ || e >= g_E) return;
    int s = g_runstart[e], t = g_runstart[e+1];
    float deg = (float)(2*(t-s) + 1);
    float xe0 = g_xe[e*3+0], xe1 = g_xe[e*3+1], xe2 = g_xe[e*3+2];
    float ax0 = xe0, ax1 = xe1, ax2 = xe2;   // self loop
    for (int i = s; i < t; i++) {
        int slot = (int)g_sv_out[i];
        int fc = slot % FN_, j = slot / FN_;
        int e1 = g_inv[((j+1)%3)*FN_ + fc];
        int e2 = g_inv[((j+2)%3)*FN_ + fc];
        ax0 += g_xe[e1*3+0] + g_xe[e2*3+0];
        ax1 += g_xe[e1*3+1] + g_xe[e2*3+1];
        ax2 += g_xe[e1*3+2] + g_xe[e2*3+2];
    }
    ax0 /= deg; ax1 /= deg; ax2 /= deg;
    float r0 = 0.f, r1 = 0.f, q0 = 0.f, q1 = 0.f;
    #pragma unroll 4
    for (int k = 0; k < HID_; k++) {
        float pre = sb[k] + xe0*s1s[k] + xe1*s1s[HID_+k] + xe2*s1s[2*HID_+k]
                          + ax0*s1n[k] + ax1*s1n[HID_+k] + ax2*s1n[2*HID_+k];
        float h = fmaxf(pre, 0.f);
        r0 += h * s2s[k];  r1 += h * s2s[HID_+k];
        q0 += h * s2n[k];  q1 += h * s2n[HID_+k];
    }
    g_rq[e*4+0] = r0; g_rq[e*4+1] = r1; g_rq[e*4+2] = q0; g_rq[e*4+3] = q1;
}

__global__ void k_gumbel(const float* __restrict__ b2) {
    int e = blockIdx.x * blockDim.x + threadIdx.x;
    if (e >= S3_) return;
    if (e == 0) { g_prefix = 0u; g_selR = g_num; }   // reset radix-select state per replay
    int E = g_E;
    if (e >= E) { g_yk[e] = 0xFFFFFFFFu; return; }
    int s = g_runstart[e], t = g_runstart[e+1];
    float deg = (float)(2*(t-s) + 1);
    float aq0 = g_rq[e*4+2], aq1 = g_rq[e*4+3];  // self loop
    for (int i = s; i < t; i++) {
        int slot = (int)g_sv_out[i];
        int fc = slot % FN_, j = slot / FN_;
        int e1 = g_inv[((j+1)%3)*FN_ + fc];
        int e2 = g_inv[((j+2)%3)*FN_ + fc];
        aq0 += g_rq[e1*4+2] + g_rq[e2*4+2];
        aq1 += g_rq[e1*4+3] + g_rq[e2*4+3];
    }
    float o0 = g_rq[e*4+0] + aq0/deg + b2[0];
    float o1 = g_rq[e*4+1] + aq1/deg + b2[1];
    float l0 = 1.f / (1.f + expf(-o0));           // sigmoid logits
    float l1 = 1.f / (1.f + expf(-o1));
    unsigned bb0 = tf_bits_part(2u*(unsigned)e);
    unsigned bb1 = tf_bits_part(2u*(unsigned)e + 1u);
    float U0 = __uint_as_float((bb0 >> 9) | 0x3F800000u) - 1.0f;
    float U1 = __uint_as_float((bb1 >> 9) | 0x3F800000u) - 1.0f;
    float gg0 = -logf(-logf(U0 + 1e-20f) + 1e-20f);
    float gg1 = -logf(-logf(U1 + 1e-20f) + 1e-20f);
    float z0 = (l0 + gg0) / 0.1f, z1 = (l1 + gg1) / 0.1f;
    float m  = fmaxf(z0, z1);
    float ez0 = expf(z0 - m), ez1 = expf(z1 - m);
    float y = ez0 / (ez0 + ez1);
    g_y[e] = y;
    // y in [0,1] => 30-bit key; smaller key == larger y. Selection = num smallest keys,
    // ties broken by ascending index (== lax.top_k on stable sort).
    g_yk[e] = (~__float_as_uint(y)) & 0x3FFFFFFFu;
}

// ---- radix-select: 4 levels of 256(64)-bucket histogram + pick ----
__global__ void k_hist(int shift, unsigned himask) {
    __shared__ int sh[256];
    sh[threadIdx.x] = 0;
    __syncthreads();
    int i = blockIdx.x * blockDim.x + threadIdx.x;
    if (i < S3_ && i < g_E) {
        unsigned key = g_yk[i];
        if ((key & himask) == (g_prefix & himask))
            atomicAdd(&sh[(key >> shift) & 0xFF], 1);
    }
    __syncthreads();
    if (sh[threadIdx.x]) atomicAdd(&g_hist[threadIdx.x], sh[threadIdx.x]);
}

__global__ void k_pick(int shift) {
    __shared__ int sc[256];
    int t = threadIdx.x;
    int c = g_hist[t];
    g_hist[t] = 0;                     // re-zero for next level / next replay
    sc[t] = c;
    __syncthreads();
    for (int d = 1; d < 256; d <<= 1) {
        int v = (t >= d) ? sc[t-d] : 0;
        __syncthreads();
        sc[t] += v;
        __syncthreads();
    }
    int k = g_selR;
    int cumin = sc[t], cumex = cumin - c;
    if (cumex < k && cumin >= k) {     // unique threshold bucket
        g_selR = k - cumex;
        g_prefix = g_prefix | ((unsigned)t << shift);
    }
}

__global__ void k_tie() {
    int i = blockIdx.x * blockDim.x + threadIdx.x;
    if (i >= S3_) return;
    g_flag[i] = (i < g_E && g_yk[i] == g_prefix) ? 1 : 0;
}

__global__ void k_sel() {
    int e = blockIdx.x * blockDim.x + threadIdx.x;
    if (e >= S3_) return;
    unsigned T = g_prefix;
    int R = g_selR;
    unsigned key = g_yk[e];
    int s = (e < g_E) && (key < T || (key == T && g_rank[e] < R));
    g_selflag[e] = s;
}

__global__ void k_cat() {
    int fc = blockIdx.x * blockDim.x + threadIdx.x;
    if (fc >= FN_) return;
    int m0 = g_selflag[g_inv[fc]];
    int m1 = g_selflag[g_inv[FN_ + fc]];
    int m2 = g_selflag[g_inv[2*FN_ + fc]];
    int pen = m0 + m1 + m2;
    int psi = m1 + 2*m2;
    int cat = (pen == 0) ? 0 : (pen == 1) ? 1 + psi : (pen == 2) ? 3 + psi : 7;
    #pragma unroll
    for (int k = 0; k < 8; k++) g_selflag[S3_ + k*FN_ + fc] = (k == cat) ? 1 : 0;
}

__device__ __forceinline__ void wtri(int row, int a, int b, int c) {
    g_nf[row*3+0] = a; g_nf[row*3+1] = b; g_nf[row*3+2] = c;
}

__global__ void k_faces(const int* __restrict__ face) {
    int fc = blockIdx.x * blockDim.x + threadIdx.x;
    if (fc >= FN_) return;
    int T0, C1, C2, T7; cat_counts(T0, C1, C2, T7);
    int num = g_num;
    int f0 = face[fc*3+0], f1 = face[fc*3+1], f2 = face[fc*3+2];
    int e0 = g_inv[fc], e1 = g_inv[FN_+fc], e2 = g_inv[2*FN_+fc];
    int m0 = g_selflag[e0], m1 = g_selflag[e1], m2 = g_selflag[e2];
    int p0 = VN_ + g_scan[e0], p1 = VN_ + g_scan[e1], p2 = VN_ + g_scan[e2];
    int pen = m0 + m1 + m2, psi = m1 + 2*m2;
    int cat = (pen == 0) ? 0 : (pen == 1) ? 1 + psi : (pen == 2) ? 3 + psi : 7;
    int pos = g_scan[S3_ + cat*FN_ + fc] - num;
    if (cat == 0) {
        wtri(pos, f0, f1, f2);
    } else if (cat <= 3) {                  // pen==1, psi = cat-1
        int g = pos - T0;
        int rA = T0 + g, rB = T0 + C1 + g;
        if (cat == 1)      { wtri(rA, f0, p0, f2); wtri(rB, p0, f1, f2); }
        else if (cat == 2) { wtri(rA, f1, p1, f0); wtri(rB, p1, f2, f0); }
        else               { wtri(rA, f2, p2, f1); wtri(rB, p2, f0, f1); }
    } else if (cat <= 6) {                  // pen==2, psi = cat-3
        int g = pos - (T0 + C1);
        int base2 = T0 + 2*C1;
        int rA = base2 + g, rB = base2 + C2 + g, rC = base2 + 2*C2 + g;
        if (cat == 4)      { wtri(rA, f0, p0, f2); wtri(rB, p0, f1, p1); wtri(rC, p0, p1, f2); }
        else if (cat == 5) { wtri(rA, f2, p2, f1); wtri(rB, p2, f0, p0); wtri(rC, p2, p0, f1); }
        else               { wtri(rA, f1, p1, f0); wtri(rB, p1, f2, p2); wtri(rC, p1, p2, f0); }
    } else {                                // pen==3
        int r = pos - (T0 + C1 + C2);
        int base3 = T0 + 2*C1 + 3*C2;
        wtri(base3 + r,        f0, p0, p2);
        wtri(base3 + T7 + r,   p0, f1, p1);
        wtri(base3 + 2*T7 + r, p0, p1, p2);
        wtri(base3 + 3*T7 + r, p1, f2, p2);
    }
}

__global__ void k_out_en(float* __restrict__ out) {
    int e = blockIdx.x * blockDim.x + threadIdx.x;
    if (e >= EMAX_ || e >= g_E) return;
    int NF = nf_total();
    int NE = VN_ + g_num + 3*NF;
    int oM = 2*g_E + 3*NF + 2*NE;
    out[2*e]   = (float)g_en0[e];
    out[2*e+1] = (float)g_en1[e];
    float y  = g_y[e];
    float yh = g_selflag[e] ? 1.f : 0.f;
    out[oM + e] = (yh - y) + y;      // straight-through mask, fp-exact formula
}

__global__ void k_out_faces(float* __restrict__ out) {
    int i = blockIdx.x * blockDim.x + threadIdx.x;
    if (i >= 3*NFMAX_) return;
    if (i >= 3*nf_total()) return;
    out[2*g_E + i] = (float)g_nf[i];
}

__global__ void k_out_edges(float* __restrict__ out) {
    int t = blockIdx.x * blockDim.x + threadIdx.x;
    if (t >= NEM_) return;
    int NF = nf_total();
    int NE = VN_ + g_num + 3*NF;
    if (t >= NE) return;
    int oNE = 2*g_E + 3*NF;
    int base = VN_ + g_num;
    int s, d;
    if (t < base) { s = t; d = t; }
    else {
        int u = t - base;
        if (u < NF)          { s = g_nf[u*3+0];        d = g_nf[u*3+1]; }
        else if (u < 2*NF)   { int r = u - NF;   s = g_nf[r*3+1]; d = g_nf[r*3+2]; }
        else                 { int r = u - 2*NF; s = g_nf[r*3+2]; d = g_nf[r*3+0]; }
    }
    out[oNE + t]      = (float)s;
    out[oNE + NE + t] = (float)d;
}

// ---------------- host ----------------
extern "C" void kernel_launch(void* const* d_in, const int* in_sizes, int n_in,
                              void* d_out, int out_size) {
    const float* x    = (const float*)d_in[0];
    const int*   face = (const int*)d_in[1];
    const int*   divp = (const int*)d_in[4];
    const float* W1s  = (const float*)d_in[5];
    const float* W1n  = (const float*)d_in[6];
    const float* b1   = (const float*)d_in[7];
    const float* W2s  = (const float*)d_in[8];
    const float* W2n  = (const float*)d_in[9];
    const float* b2   = (const float*)d_in[10];
    float* out = (float*)d_out;

    void *tp, *psk_in, *psk_out, *psv_in, *psv_out, *pflag, *prank, *pselflag, *pscan;
    cudaGetSymbolAddress(&tp,      g_temp);
    cudaGetSymbolAddress(&psk_in,  g_sk_in);
    cudaGetSymbolAddress(&psk_out, g_sk_out);
    cudaGetSymbolAddress(&psv_in,  g_sv_in);
    cudaGetSymbolAddress(&psv_out, g_sv_out);
    cudaGetSymbolAddress(&pflag,   g_flag);
    cudaGetSymbolAddress(&prank,   g_rank);
    cudaGetSymbolAddress(&pselflag,g_selflag);
    cudaGetSymbolAddress(&pscan,   g_scan);
    cudaStream_t st = 0;
    size_t tb;

    k_build_keys<<<GS3, TPB, 0, st>>>(face);

    tb = sizeof(g_temp);
    cub::DeviceRadixSort::SortPairs(tp, tb,
        (const unsigned*)psk_in, (unsigned*)psk_out,
        (const unsigned*)psv_in, (unsigned*)psv_out, S3_, 0, 32, st);

    k_head<<<GS3, TPB, 0, st>>>();
    tb = sizeof(g_temp);
    cub::DeviceScan::InclusiveSum(tp, tb, (const int*)pflag, (int*)prank, S3_, st);
    k_unique<<<GS3, TPB, 0, st>>>(x, divp);
    k_gnn1<<<GS3, TPB, 0, st>>>(W1s, W1n, b1, W2s, W2n);
    k_gumbel<<<GS3, TPB, 0, st>>>(b2);

    // radix-select: exact threshold key T + residual tie count R (replaces full sort)
    k_hist<<<GS3, TPB, 0, st>>>(24, 0x00000000u); k_pick<<<1, 256, 0, st>>>(24);
    k_hist<<<GS3, TPB, 0, st>>>(16, 0x3F000000u); k_pick<<<1, 256, 0, st>>>(16);
    k_hist<<<GS3, TPB, 0, st>>>( 8, 0x3FFF0000u); k_pick<<<1, 256, 0, st>>>( 8);
    k_hist<<<GS3, TPB, 0, st>>>( 0, 0x3FFFFF00u); k_pick<<<1, 256, 0, st>>>( 0);
    // index-ordered rank among ties (stable top_k tie-break)
    k_tie<<<GS3, TPB, 0, st>>>();
    tb = sizeof(g_temp);
    cub::DeviceScan::ExclusiveSum(tp, tb, (const int*)pflag, (int*)prank, S3_, st);
    k_sel<<<GS3, TPB, 0, st>>>();

    k_cat<<<GF, TPB, 0, st>>>();
    // one combined scan: sel (pool ranks) + 8-category face flags
    tb = sizeof(g_temp);
    cub::DeviceScan::ExclusiveSum(tp, tb, (const int*)pselflag, (int*)pscan, SF_, st);
    k_faces<<<GF, TPB, 0, st>>>(face);

    k_out_en<<<GS3, TPB, 0, st>>>(out);
    k_out_faces<<<GNF3, TPB, 0, st>>>(out);
    k_out_edges<<<GNE, TPB, 0, st>>>(out);
}

// round 7
// speedup vs baseline: 1.2679x; 1.0299x over previous
#include <cuda_runtime.h>
#include <cstdint>
#include <cub/cub.cuh>

#define VN_    50000
#define FN_    100000
#define S3_    (3*FN_)
#define EMAX_  S3_
#define HID_   256
#define NFMAX_ (4*FN_)
#define PEMAX_ ((S3_/5)+64)
#define NEM_   (VN_ + PEMAX_ + 3*NFMAX_)
#define SF_    (S3_ + 8*FN_)          // combined sel+flag8 scan length
#define TPB    256
#define GS3    ((S3_ + TPB - 1)/TPB)
#define GF     ((FN_ + TPB - 1)/TPB)
#define GNE    ((NEM_ + TPB - 1)/TPB)
#define GNF3   ((3*NFMAX_ + TPB - 1)/TPB)

// ---------------- static device scratch (no allocation allowed) ----------------
__device__ unsigned g_sk_in[S3_], g_sk_out[S3_], g_sv_in[S3_], g_sv_out[S3_];
__device__ int g_flag[S3_], g_rank[S3_], g_inv[S3_];
__device__ int g_runstart[EMAX_+1];
__device__ int g_en0[EMAX_], g_en1[EMAX_];
__device__ float g_xe[EMAX_*3];
__device__ float g_rq[EMAX_*4];      // r0,r1,q0,q1 per edge
__device__ float g_y[EMAX_];
__device__ unsigned g_yk[S3_];       // 30-bit selection keys (~float_bits(y))
__device__ int g_selflag[SF_];       // [0,S3_): sel ; [S3_,S3_+8FN): flag8
__device__ int g_scan[SF_];          // exclusive scan of g_selflag
__device__ int g_nf[3*NFMAX_];
__device__ int g_histK[1024];        // key-select histogram (picks re-zero)
__device__ int g_histI[1024];        // index-select histogram (picks re-zero)
__device__ unsigned g_T;             // threshold key (30-bit, resolved over 3 levels)
__device__ int g_RK;                 // remaining count within key threshold
__device__ unsigned g_I;             // threshold tie index I* (19-bit, 2 levels)
__device__ int g_RI;                 // remaining count within index level
__device__ int g_E, g_num;
__device__ unsigned char g_temp[48u<<20];

// ---------------- threefry2x32, key = (0,42), JAX-exact ----------------
__device__ __forceinline__ unsigned rotl32(unsigned v, int d) {
    return (v << d) | (v >> (32 - d));
}
__device__ __forceinline__ void threefry_0_42(unsigned x0, unsigned x1,
                                              unsigned& o0, unsigned& o1) {
    const unsigned k0 = 0u, k1 = 42u;
    const unsigned ks2 = k0 ^ k1 ^ 0x1BD11BDAu;
    x0 += k0; x1 += k1;
#define TF4(a,b,c,d) \
    x0 += x1; x1 = rotl32(x1,a); x1 ^= x0; \
    x0 += x1; x1 = rotl32(x1,b); x1 ^= x0; \
    x0 += x1; x1 = rotl32(x1,c); x1 ^= x0; \
    x0 += x1; x1 = rotl32(x1,d); x1 ^= x0;
    TF4(13,15,26,6);   x0 += k1;  x1 += ks2 + 1u;
    TF4(17,29,16,24);  x0 += ks2; x1 += k0  + 2u;
    TF4(13,15,26,6);   x0 += k0;  x1 += k1  + 3u;
    TF4(17,29,16,24);  x0 += k1;  x1 += ks2 + 4u;
    TF4(13,15,26,6);   x0 += ks2; x1 += k0  + 5u;
#undef TF4
    o0 = x0; o1 = x1;
}
// Partitionable-threefry random bits (JAX >= 0.5 default):
// bits32[i] = o0 ^ o1 with (o0,o1) = threefry((0,42), (0, i))
__device__ __forceinline__ unsigned tf_bits_part(unsigned i) {
    unsigned o0, o1;
    threefry_0_42(0u, i, o0, o1);
    return o0 ^ o1;
}

// derived category counts from the combined scan (cheap, L2-broadcast loads)
__device__ __forceinline__ void cat_counts(int& T0, int& C1, int& C2, int& T7) {
    int num = g_num;
    int P1 = g_scan[S3_ +   FN_] - num;
    int P4 = g_scan[S3_ + 4*FN_] - num;
    int P7 = g_scan[S3_ + 7*FN_] - num;
    T0 = P1; C1 = P4 - P1; C2 = P7 - P4; T7 = FN_ - P7;
}
__device__ __forceinline__ int nf_total() {
    int T0, C1, C2, T7; cat_counts(T0, C1, C2, T7);
    return T0 + 2*C1 + 3*C2 + 4*T7;
}

// ---------------- kernels ----------------
__global__ void k_build_keys(const int* __restrict__ face) {
    int i = blockIdx.x * blockDim.x + threadIdx.x;
    if (i >= S3_) return;
    int blk = i / FN_, fc = i - blk * FN_;
    int a, b;
    if (blk == 0)      { a = face[fc*3+0]; b = face[fc*3+1]; }
    else if (blk == 1) { a = face[fc*3+1]; b = face[fc*3+2]; }
    else               { a = face[fc*3+2]; b = face[fc*3+0]; }
    int lo = min(a, b), hi = max(a, b);
    int key = (int)((unsigned)lo * (unsigned)VN_ + (unsigned)hi); // int32 wrap like JAX
    g_sk_in[i] = (unsigned)key ^ 0x80000000u;  // signed order under unsigned radix
    g_sv_in[i] = (unsigned)i;
}

__global__ void k_head() {
    int i = blockIdx.x * blockDim.x + threadIdx.x;
    if (i >= S3_) return;
    g_flag[i] = (i == 0 || g_sk_out[i] != g_sk_out[i-1]) ? 1 : 0;
}

// unique + inverse map + scalars + edge-node endpoints + xe, all fused
__global__ void k_unique(const float* __restrict__ x, const int* __restrict__ divp) {
    int i = blockIdx.x * blockDim.x + threadIdx.x;
    if (i >= S3_) return;
    int r = g_rank[i];                 // inclusive scan of flags
    if (g_flag[i]) {
        int e = r - 1;
        g_runstart[e] = i;
        int k = (int)(g_sk_out[i] ^ 0x80000000u);
        int q = k / VN_, rm = k % VN_;     // C trunc -> numpy floor fixup
        if (rm < 0) { rm += VN_; q -= 1; }
        g_en0[e] = q; g_en1[e] = rm;
        int i0 = (q < 0) ? q + VN_ : q;    // JAX gather: negative wrap, then clamp
        if (i0 < 0) i0 = 0;
        if (i0 >= VN_) i0 = VN_ - 1;
        #pragma unroll
        for (int c = 0; c < 3; c++)
            g_xe[e*3+c] = 0.5f * (x[i0*3+c] + x[rm*3+c]);
    }
    g_inv[g_sv_out[i]] = r - 1;
    if (i == S3_ - 1) { g_E = r; g_runstart[r] = S3_; g_num = r / divp[0]; }
}

__global__ void k_gnn1(const float* __restrict__ W1s, const float* __restrict__ W1n,
                       const float* __restrict__ b1,  const float* __restrict__ W2s,
                       const float* __restrict__ W2n) {
    __shared__ float s1s[3*HID_], s1n[3*HID_], sb[HID_], s2s[2*HID_], s2n[2*HID_];
    for (int i = threadIdx.x; i < 3*HID_; i += blockDim.x) { s1s[i] = W1s[i]; s1n[i] = W1n[i]; }
    for (int i = threadIdx.x; i < HID_;   i += blockDim.x) {
        sb[i] = b1[i];
        s2s[i] = W2s[i*2+0]; s2s[HID_+i] = W2s[i*2+1];
        s2n[i] = W2n[i*2+0]; s2n[HID_+i] = W2n[i*2+1];
    }
    __syncthreads();
    int e = blockIdx.x * blockDim.x + threadIdx.x;
    if (e >= EMAX_ || e >= g_E) return;
    int s = g_runstart[e], t = g_runstart[e+1];
    float deg = (float)(2*(t-s) + 1);
    float xe0 = g_xe[e*3+0], xe1 = g_xe[e*3+1], xe2 = g_xe[e*3+2];
    float ax0 = xe0, ax1 = xe1, ax2 = xe2;   // self loop
    for (int i = s; i < t; i++) {
        int slot = (int)g_sv_out[i];
        int fc = slot % FN_, j = slot / FN_;
        int e1 = g_inv[((j+1)%3)*FN_ + fc];
        int e2 = g_inv[((j+2)%3)*FN_ + fc];
        ax0 += g_xe[e1*3+0] + g_xe[e2*3+0];
        ax1 += g_xe[e1*3+1] + g_xe[e2*3+1];
        ax2 += g_xe[e1*3+2] + g_xe[e2*3+2];
    }
    ax0 /= deg; ax1 /= deg; ax2 /= deg;
    float r0 = 0.f, r1 = 0.f, q0 = 0.f, q1 = 0.f;
    #pragma unroll 4
    for (int k = 0; k < HID_; k++) {
        float pre = sb[k] + xe0*s1s[k] + xe1*s1s[HID_+k] + xe2*s1s[2*HID_+k]
                          + ax0*s1n[k] + ax1*s1n[HID_+k] + ax2*s1n[2*HID_+k];
        float h = fmaxf(pre, 0.f);
        r0 += h * s2s[k];  r1 += h * s2s[HID_+k];
        q0 += h * s2n[k];  q1 += h * s2n[HID_+k];
    }
    g_rq[e*4+0] = r0; g_rq[e*4+1] = r1; g_rq[e*4+2] = q0; g_rq[e*4+3] = q1;
}

__global__ void k_gumbel(const float* __restrict__ b2) {
    int e = blockIdx.x * blockDim.x + threadIdx.x;
    if (e >= S3_) return;
    int E = g_E;
    if (e >= E) { g_yk[e] = 0xFFFFFFFFu; return; }
    int s = g_runstart[e], t = g_runstart[e+1];
    float deg = (float)(2*(t-s) + 1);
    float aq0 = g_rq[e*4+2], aq1 = g_rq[e*4+3];  // self loop
    for (int i = s; i < t; i++) {
        int slot = (int)g_sv_out[i];
        int fc = slot % FN_, j = slot / FN_;
        int e1 = g_inv[((j+1)%3)*FN_ + fc];
        int e2 = g_inv[((j+2)%3)*FN_ + fc];
        aq0 += g_rq[e1*4+2] + g_rq[e2*4+2];
        aq1 += g_rq[e1*4+3] + g_rq[e2*4+3];
    }
    float o0 = g_rq[e*4+0] + aq0/deg + b2[0];
    float o1 = g_rq[e*4+1] + aq1/deg + b2[1];
    float l0 = 1.f / (1.f + expf(-o0));           // sigmoid logits
    float l1 = 1.f / (1.f + expf(-o1));
    unsigned bb0 = tf_bits_part(2u*(unsigned)e);
    unsigned bb1 = tf_bits_part(2u*(unsigned)e + 1u);
    float U0 = __uint_as_float((bb0 >> 9) | 0x3F800000u) - 1.0f;
    float U1 = __uint_as_float((bb1 >> 9) | 0x3F800000u) - 1.0f;
    float gg0 = -logf(-logf(U0 + 1e-20f) + 1e-20f);
    float gg1 = -logf(-logf(U1 + 1e-20f) + 1e-20f);
    float z0 = (l0 + gg0) / 0.1f, z1 = (l1 + gg1) / 0.1f;
    float m  = fmaxf(z0, z1);
    float ez0 = expf(z0 - m), ez1 = expf(z1 - m);
    float y = ez0 / (ez0 + ez1);
    g_y[e] = y;
    // y in [0,1] => 30-bit key; smaller key == larger y. Selection = num smallest keys,
    // ties broken by ascending index (== lax.top_k on stable radix sort).
    g_yk[e] = (~__float_as_uint(y)) & 0x3FFFFFFFu;
}

// ---- radix-select over keys: 3 levels x 10 bits (smem-privatized histograms) ----
// matchshift >= 30 compares 0==0 (always true; also immune to stale g_T at level 1).
__global__ void k_histK(int shift, int matchshift) {
    __shared__ int sh[1024];
    for (int j = threadIdx.x; j < 1024; j += blockDim.x) sh[j] = 0;
    __syncthreads();
    int i = blockIdx.x * blockDim.x + threadIdx.x;
    if (i < S3_ && i < g_E) {
        unsigned key = g_yk[i];
        if ((key >> matchshift) == (g_T >> matchshift))
            atomicAdd(&sh[(key >> shift) & 1023], 1);
    }
    __syncthreads();
    for (int j = threadIdx.x; j < 1024; j += blockDim.x)
        if (sh[j]) atomicAdd(&g_histK[j], sh[j]);
}

// ---- radix-select over tie indices: 2 levels (10 + 9 bits) ----
__global__ void k_histI(int shift, int matchshift, int bmask) {
    __shared__ int sh[1024];
    for (int j = threadIdx.x; j < 1024; j += blockDim.x) sh[j] = 0;
    __syncthreads();
    int i = blockIdx.x * blockDim.x + threadIdx.x;
    if (i < S3_ && i < g_E && g_yk[i] == g_T) {
        unsigned u = (unsigned)i;
        if ((u >> matchshift) == (g_I >> matchshift))
            atomicAdd(&sh[(u >> shift) & bmask], 1);
    }
    __syncthreads();
    for (int j = threadIdx.x; j < 1024; j += blockDim.x)
        if (sh[j]) atomicAdd(&g_histI[j], sh[j]);
}

// generic pick: scans nb buckets, finds crossing of k, updates state, re-zeros hist.
// kind: 0 = key level1 (k=g_num, assign T)   1 = key later (k=g_RK, OR into T)
//       2 = idx level1 (k=g_RK, assign I)    3 = idx later (k=g_RI, OR into I)
__global__ void k_pick(int* hist, int nb, int shift, int kind) {
    int t = threadIdx.x;
    int per = nb >> 8;                  // buckets per thread (256 threads)
    int base = t * per;
    int vals[4];
    int local = 0;
    for (int j = 0; j < per; j++) { vals[j] = hist[base+j]; hist[base+j] = 0; local += vals[j]; }
    __shared__ int sc[256];
    sc[t] = local;
    __syncthreads();
    for (int d = 1; d < 256; d <<= 1) {
        int v = (t >= d) ? sc[t-d] : 0;
        __syncthreads();
        sc[t] += v;
        __syncthreads();
    }
    int k = (kind == 0) ? g_num : (kind == 3) ? g_RI : g_RK;
    int cumex = sc[t] - local;
    if (cumex < k && sc[t] >= k) {      // crossing lies in my bucket range
        int c = cumex;
        for (int j = 0; j < per; j++) {
            if (c + vals[j] >= k) {
                unsigned b = (unsigned)(base + j);
                int rem = k - c;
                if (kind == 0)      { g_T = b << shift; g_RK = rem; }
                else if (kind == 1) { g_T |= b << shift; g_RK = rem; }
                else if (kind == 2) { g_I = b << shift; g_RI = rem; }
                else                { g_I |= b << shift; }
                break;
            }
            c += vals[j];
        }
    }
}

__global__ void k_sel() {
    int e = blockIdx.x * blockDim.x + threadIdx.x;
    if (e >= S3_) return;
    unsigned T = g_T, I = g_I;
    unsigned key = g_yk[e];
    g_selflag[e] = (e < g_E) && (key < T || (key == T && (unsigned)e <= I));
}

__global__ void k_cat() {
    int fc = blockIdx.x * blockDim.x + threadIdx.x;
    if (fc >= FN_) return;
    int m0 = g_selflag[g_inv[fc]];
    int m1 = g_selflag[g_inv[FN_ + fc]];
    int m2 = g_selflag[g_inv[2*FN_ + fc]];
    int pen = m0 + m1 + m2;
    int psi = m1 + 2*m2;
    int cat = (pen == 0) ? 0 : (pen == 1) ? 1 + psi : (pen == 2) ? 3 + psi : 7;
    #pragma unroll
    for (int k = 0; k < 8; k++) g_selflag[S3_ + k*FN_ + fc] = (k == cat) ? 1 : 0;
}

__device__ __forceinline__ void wtri(int row, int a, int b, int c) {
    g_nf[row*3+0] = a; g_nf[row*3+1] = b; g_nf[row*3+2] = c;
}

__global__ void k_faces(const int* __restrict__ face) {
    int fc = blockIdx.x * blockDim.x + threadIdx.x;
    if (fc >= FN_) return;
    int T0, C1, C2, T7; cat_counts(T0, C1, C2, T7);
    int num = g_num;
    int f0 = face[fc*3+0], f1 = face[fc*3+1], f2 = face[fc*3+2];
    int e0 = g_inv[fc], e1 = g_inv[FN_+fc], e2 = g_inv[2*FN_+fc];
    int m0 = g_selflag[e0], m1 = g_selflag[e1], m2 = g_selflag[e2];
    int p0 = VN_ + g_scan[e0], p1 = VN_ + g_scan[e1], p2 = VN_ + g_scan[e2];
    int pen = m0 + m1 + m2, psi = m1 + 2*m2;
    int cat = (pen == 0) ? 0 : (pen == 1) ? 1 + psi : (pen == 2) ? 3 + psi : 7;
    int pos = g_scan[S3_ + cat*FN_ + fc] - num;
    if (cat == 0) {
        wtri(pos, f0, f1, f2);
    } else if (cat <= 3) {                  // pen==1, psi = cat-1
        int g = pos - T0;
        int rA = T0 + g, rB = T0 + C1 + g;
        if (cat == 1)      { wtri(rA, f0, p0, f2); wtri(rB, p0, f1, f2); }
        else if (cat == 2) { wtri(rA, f1, p1, f0); wtri(rB, p1, f2, f0); }
        else               { wtri(rA, f2, p2, f1); wtri(rB, p2, f0, f1); }
    } else if (cat <= 6) {                  // pen==2, psi = cat-3
        int g = pos - (T0 + C1);
        int base2 = T0 + 2*C1;
        int rA = base2 + g, rB = base2 + C2 + g, rC = base2 + 2*C2 + g;
        if (cat == 4)      { wtri(rA, f0, p0, f2); wtri(rB, p0, f1, p1); wtri(rC, p0, p1, f2); }
        else if (cat == 5) { wtri(rA, f2, p2, f1); wtri(rB, p2, f0, p0); wtri(rC, p2, p0, f1); }
        else               { wtri(rA, f1, p1, f0); wtri(rB, p1, f2, p2); wtri(rC, p1, p2, f0); }
    } else {                                // pen==3
        int r = pos - (T0 + C1 + C2);
        int base3 = T0 + 2*C1 + 3*C2;
        wtri(base3 + r,        f0, p0, p2);
        wtri(base3 + T7 + r,   p0, f1, p1);
        wtri(base3 + 2*T7 + r, p0, p1, p2);
        wtri(base3 + 3*T7 + r, p1, f2, p2);
    }
}

// all three output sections in one launch (block-range dispatch)
__global__ void k_outputs(float* __restrict__ out) {
    int b = blockIdx.x;
    if (b < GS3) {
        int e = b * TPB + threadIdx.x;
        if (e >= EMAX_ || e >= g_E) return;
        int NF = nf_total();
        int NE = VN_ + g_num + 3*NF;
        int oM = 2*g_E + 3*NF + 2*NE;
        out[2*e]   = (float)g_en0[e];
        out[2*e+1] = (float)g_en1[e];
        float y  = g_y[e];
        float yh = g_selflag[e] ? 1.f : 0.f;
        out[oM + e] = (yh - y) + y;      // straight-through mask, fp-exact formula
    } else if (b < GS3 + GNF3) {
        int i = (b - GS3) * TPB + threadIdx.x;
        if (i >= 3*NFMAX_ || i >= 3*nf_total()) return;
        out[2*g_E + i] = (float)g_nf[i];
    } else {
        int t = (b - GS3 - GNF3) * TPB + threadIdx.x;
        if (t >= NEM_) return;
        int NF = nf_total();
        int NE = VN_ + g_num + 3*NF;
        if (t >= NE) return;
        int oNE = 2*g_E + 3*NF;
        int base = VN_ + g_num;
        int s, d;
        if (t < base) { s = t; d = t; }
        else {
            int u = t - base;
            if (u < NF)          { s = g_nf[u*3+0];        d = g_nf[u*3+1]; }
            else if (u < 2*NF)   { int r = u - NF;   s = g_nf[r*3+1]; d = g_nf[r*3+2]; }
            else                 { int r = u - 2*NF; s = g_nf[r*3+2]; d = g_nf[r*3+0]; }
        }
        out[oNE + t]      = (float)s;
        out[oNE + NE + t] = (float)d;
    }
}

// ---------------- host ----------------
extern "C" void kernel_launch(void* const* d_in, const int* in_sizes, int n_in,
                              void* d_out, int out_size) {
    const float* x    = (const float*)d_in[0];
    const int*   face = (const int*)d_in[1];
    const int*   divp = (const int*)d_in[4];
    const float* W1s  = (const float*)d_in[5];
    const float* W1n  = (const float*)d_in[6];
    const float* b1   = (const float*)d_in[7];
    const float* W2s  = (const float*)d_in[8];
    const float* W2n  = (const float*)d_in[9];
    const float* b2   = (const float*)d_in[10];
    float* out = (float*)d_out;

    void *tp, *psk_in, *psk_out, *psv_in, *psv_out, *pflag, *prank;
    void *pselflag, *pscan, *phistK, *phistI;
    cudaGetSymbolAddress(&tp,      g_temp);
    cudaGetSymbolAddress(&psk_in,  g_sk_in);
    cudaGetSymbolAddress(&psk_out, g_sk_out);
    cudaGetSymbolAddress(&psv_in,  g_sv_in);
    cudaGetSymbolAddress(&psv_out, g_sv_out);
    cudaGetSymbolAddress(&pflag,   g_flag);
    cudaGetSymbolAddress(&prank,   g_rank);
    cudaGetSymbolAddress(&pselflag,g_selflag);
    cudaGetSymbolAddress(&pscan,   g_scan);
    cudaGetSymbolAddress(&phistK,  g_histK);
    cudaGetSymbolAddress(&phistI,  g_histI);
    cudaStream_t st = 0;
    size_t tb;

    k_build_keys<<<GS3, TPB, 0, st>>>(face);

    tb = sizeof(g_temp);
    cub::DeviceRadixSort::SortPairs(tp, tb,
        (const unsigned*)psk_in, (unsigned*)psk_out,
        (const unsigned*)psv_in, (unsigned*)psv_out, S3_, 0, 32, st);

    k_head<<<GS3, TPB, 0, st>>>();
    tb = sizeof(g_temp);
    cub::DeviceScan::InclusiveSum(tp, tb, (const int*)pflag, (int*)prank, S3_, st);
    k_unique<<<GS3, TPB, 0, st>>>(x, divp);
    k_gnn1<<<GS3, TPB, 0, st>>>(W1s, W1n, b1, W2s, W2n);
    k_gumbel<<<GS3, TPB, 0, st>>>(b2);

    // key radix-select: 3 x 10 bits -> threshold key T + residual tie count R
    k_histK<<<GS3, TPB, 0, st>>>(20, 30); k_pick<<<1, 256, 0, st>>>((int*)phistK, 1024, 20, 0);
    k_histK<<<GS3, TPB, 0, st>>>(10, 20); k_pick<<<1, 256, 0, st>>>((int*)phistK, 1024, 10, 1);
    k_histK<<<GS3, TPB, 0, st>>>( 0, 10); k_pick<<<1, 256, 0, st>>>((int*)phistK, 1024,  0, 1);
    // tie-break radix-select over edge index (unique) -> I* = R-th smallest tie index
    k_histI<<<GS3, TPB, 0, st>>>(9, 19, 1023); k_pick<<<1, 256, 0, st>>>((int*)phistI, 1024, 9, 2);
    k_histI<<<GS3, TPB, 0, st>>>(0,  9,  511); k_pick<<<1, 256, 0, st>>>((int*)phistI,  512, 0, 3);
    k_sel<<<GS3, TPB, 0, st>>>();

    k_cat<<<GF, TPB, 0, st>>>();
    // one combined scan: sel (pool ranks) + 8-category face flags
    tb = sizeof(g_temp);
    cub::DeviceScan::ExclusiveSum(tp, tb, (const int*)pselflag, (int*)pscan, SF_, st);
    k_faces<<<GF, TPB, 0, st>>>(face);

    k_outputs<<<GS3 + GNF3 + GNE, TPB, 0, st>>>(out);
}

// round 9
// speedup vs baseline: 1.2802x; 1.0097x over previous
#include <cuda_runtime.h>
#include <cstdint>
#include <cub/cub.cuh>

#define VN_    50000
#define FN_    100000
#define S3_    (3*FN_)
#define EMAX_  S3_
#define HID_   256
#define NFMAX_ (4*FN_)
#define PEMAX_ ((S3_/5)+64)
#define NEM_   (VN_ + PEMAX_ + 3*NFMAX_)
#define SF_    (S3_ + 8*FN_)          // combined sel+flag8 scan length
#define TPB    256
#define GS3    ((S3_ + TPB - 1)/TPB)  // 1172
#define GF     ((FN_ + TPB - 1)/TPB)
#define GNE    ((NEM_ + TPB - 1)/TPB)
#define GNF3   ((3*NFMAX_ + TPB - 1)/TPB)
#define NCHS   GS3

// ---------------- static device scratch (no allocation allowed) ----------------
__device__ unsigned g_sk_in[S3_], g_sk_out[S3_], g_sv_in[S3_], g_sv_out[S3_];
__device__ int g_rank[S3_], g_inv[S3_];
__device__ int g_chU[NCHS], g_offU[NCHS];
__device__ int g_runstart[EMAX_+1];
__device__ int g_en0[EMAX_], g_en1[EMAX_];
__device__ float g_xe[EMAX_*3];
__device__ float g_rq[EMAX_*4];      // r0,r1,q0,q1 per edge
__device__ float g_y[EMAX_];
__device__ unsigned g_yk[S3_];       // 30-bit selection keys (~float_bits(y))
__device__ int g_selflag[SF_];       // [0,S3_): sel ; [S3_,S3_+8FN): flag8
__device__ int g_scan[SF_];          // exclusive scan of g_selflag
__device__ int g_nf[3*NFMAX_];
__device__ int g_histK[1024];        // key-select histogram (picks re-zero)
__device__ int g_histI[1024];        // index-select histogram (picks re-zero)
__device__ unsigned g_T;             // threshold key (30-bit)
__device__ int g_RK;                 // remaining count within key threshold
__device__ unsigned g_I;             // tie threshold index I* (19-bit)
__device__ int g_RI;
__device__ unsigned g_done = 0;      // last-block-done counter (self-resets)
__device__ int g_E, g_num;
__device__ unsigned char g_temp[48u<<20];

// ---------------- threefry2x32, key = (0,42), JAX-exact ----------------
__device__ __forceinline__ unsigned rotl32(unsigned v, int d) {
    return (v << d) | (v >> (32 - d));
}
__device__ __forceinline__ void threefry_0_42(unsigned x0, unsigned x1,
                                              unsigned& o0, unsigned& o1) {
    const unsigned k0 = 0u, k1 = 42u;
    const unsigned ks2 = k0 ^ k1 ^ 0x1BD11BDAu;
    x0 += k0; x1 += k1;
#define TF4(a,b,c,d) \
    x0 += x1; x1 = rotl32(x1,a); x1 ^= x0; \
    x0 += x1; x1 = rotl32(x1,b); x1 ^= x0; \
    x0 += x1; x1 = rotl32(x1,c); x1 ^= x0; \
    x0 += x1; x1 = rotl32(x1,d); x1 ^= x0;
    TF4(13,15,26,6);   x0 += k1;  x1 += ks2 + 1u;
    TF4(17,29,16,24);  x0 += ks2; x1 += k0  + 2u;
    TF4(13,15,26,6);   x0 += k0;  x1 += k1  + 3u;
    TF4(17,29,16,24);  x0 += k1;  x1 += ks2 + 4u;
    TF4(13,15,26,6);   x0 += ks2; x1 += k0  + 5u;
#undef TF4
    o0 = x0; o1 = x1;
}
// Partitionable-threefry (JAX >= 0.5 default): bits[i] = xor(threefry((0,42),(0,i)))
__device__ __forceinline__ unsigned tf_bits_part(unsigned i) {
    unsigned o0, o1;
    threefry_0_42(0u, i, o0, o1);
    return o0 ^ o1;
}

// exclusive in-block binary prefix over 256 threads; also returns block total
__device__ __forceinline__ int blk_prefix(int flag, int* wsum, int* total) {
    unsigned m = __ballot_sync(0xFFFFFFFFu, flag != 0);
    int lane = threadIdx.x & 31, w = threadIdx.x >> 5;
    int excl = __popc(m & ((1u << lane) - 1u));
    if (lane == 0) wsum[w] = __popc(m);
    __syncthreads();
    int off = 0, tot = 0;
    #pragma unroll
    for (int j = 0; j < 8; j++) { int v = wsum[j]; tot += v; if (j < w) off += v; }
    *total = tot;
    __syncthreads();
    return excl + off;
}

// derived category counts from the combined scan (R7-proven)
__device__ __forceinline__ void cat_counts(int& T0, int& C1, int& C2, int& T7) {
    int num = g_num;
    int P1 = g_scan[S3_ +   FN_] - num;
    int P4 = g_scan[S3_ + 4*FN_] - num;
    int P7 = g_scan[S3_ + 7*FN_] - num;
    T0 = P1; C1 = P4 - P1; C2 = P7 - P4; T7 = FN_ - P7;
}
__device__ __forceinline__ int nf_total() {
    int T0, C1, C2, T7; cat_counts(T0, C1, C2, T7);
    return T0 + 2*C1 + 3*C2 + 4*T7;
}

// ---------------- kernels ----------------
__global__ void k_build_keys(const int* __restrict__ face) {
    int i = blockIdx.x * blockDim.x + threadIdx.x;
    if (i >= S3_) return;
    int blk = i / FN_, fc = i - blk * FN_;
    int a, b;
    if (blk == 0)      { a = face[fc*3+0]; b = face[fc*3+1]; }
    else if (blk == 1) { a = face[fc*3+1]; b = face[fc*3+2]; }
    else               { a = face[fc*3+2]; b = face[fc*3+0]; }
    int lo = min(a, b), hi = max(a, b);
    int key = (int)((unsigned)lo * (unsigned)VN_ + (unsigned)hi); // int32 wrap like JAX
    g_sk_in[i] = (unsigned)key ^ 0x80000000u;  // signed order under unsigned radix
    g_sv_in[i] = (unsigned)i;
}

// head flags + in-chunk inclusive prefix + chunk totals (validated in R8 via output 0)
__global__ void k_head() {
    __shared__ int wsum[8];
    int i = blockIdx.x * blockDim.x + threadIdx.x;
    int flag = (i < S3_) && (i == 0 || g_sk_out[i] != g_sk_out[i-1]);
    int tot;
    int excl = blk_prefix(flag, wsum, &tot);
    if (i < S3_) g_rank[i] = excl + flag;   // in-chunk inclusive
    if (threadIdx.x == 0) g_chU[blockIdx.x] = tot;
}

// single-block exclusive scan of chunk totals
__global__ void k_tiny1() {
    __shared__ int part[1024];
    int t = threadIdx.x;
    int a0 = (2*t   < NCHS) ? g_chU[2*t]   : 0;
    int a1 = (2*t+1 < NCHS) ? g_chU[2*t+1] : 0;
    part[t] = a0 + a1;
    __syncthreads();
    for (int d = 1; d < 1024; d <<= 1) {
        int v = (t >= d) ? part[t-d] : 0;
        __syncthreads();
        part[t] += v;
        __syncthreads();
    }
    int base = t ? part[t-1] : 0;
    if (2*t   < NCHS) g_offU[2*t]   = base;
    if (2*t+1 < NCHS) g_offU[2*t+1] = base + a0;
}

// unique + inverse map + scalars + edge-node endpoints + xe, fused
__global__ void k_unique(const float* __restrict__ x, const int* __restrict__ divp) {
    int i = blockIdx.x * blockDim.x + threadIdx.x;
    if (i >= S3_) return;
    int r = g_offU[blockIdx.x] + g_rank[i];   // global inclusive rank
    int flag = (i == 0 || g_sk_out[i] != g_sk_out[i-1]);
    if (flag) {
        int e = r - 1;
        g_runstart[e] = i;
        int k = (int)(g_sk_out[i] ^ 0x80000000u);
        int q = k / VN_, rm = k % VN_;     // C trunc -> numpy floor fixup
        if (rm < 0) { rm += VN_; q -= 1; }
        g_en0[e] = q; g_en1[e] = rm;
        int i0 = (q < 0) ? q + VN_ : q;    // JAX gather: negative wrap, then clamp
        if (i0 < 0) i0 = 0;
        if (i0 >= VN_) i0 = VN_ - 1;
        #pragma unroll
        for (int c = 0; c < 3; c++)
            g_xe[e*3+c] = 0.5f * (x[i0*3+c] + x[rm*3+c]);
    }
    g_inv[g_sv_out[i]] = r - 1;
    if (i == S3_ - 1) { g_E = r; g_runstart[r] = S3_; g_num = r / divp[0]; }
}

__global__ void k_gnn1(const float* __restrict__ W1s, const float* __restrict__ W1n,
                       const float* __restrict__ b1,  const float* __restrict__ W2s,
                       const float* __restrict__ W2n) {
    __shared__ float s1s[3*HID_], s1n[3*HID_], sb[HID_], s2s[2*HID_], s2n[2*HID_];
    for (int i = threadIdx.x; i < 3*HID_; i += blockDim.x) { s1s[i] = W1s[i]; s1n[i] = W1n[i]; }
    for (int i = threadIdx.x; i < HID_;   i += blockDim.x) {
        sb[i] = b1[i];
        s2s[i] = W2s[i*2+0]; s2s[HID_+i] = W2s[i*2+1];
        s2n[i] = W2n[i*2+0]; s2n[HID_+i] = W2n[i*2+1];
    }
    __syncthreads();
    int e = blockIdx.x * blockDim.x + threadIdx.x;
    if (e >= EMAX_ || e >= g_E) return;
    int s = g_runstart[e], t = g_runstart[e+1];
    float deg = (float)(2*(t-s) + 1);
    float xe0 = g_xe[e*3+0], xe1 = g_xe[e*3+1], xe2 = g_xe[e*3+2];
    float ax0 = xe0, ax1 = xe1, ax2 = xe2;   // self loop
    for (int i = s; i < t; i++) {
        int slot = (int)g_sv_out[i];
        int fc = slot % FN_, j = slot / FN_;
        int e1 = g_inv[((j+1)%3)*FN_ + fc];
        int e2 = g_inv[((j+2)%3)*FN_ + fc];
        ax0 += g_xe[e1*3+0] + g_xe[e2*3+0];
        ax1 += g_xe[e1*3+1] + g_xe[e2*3+1];
        ax2 += g_xe[e1*3+2] + g_xe[e2*3+2];
    }
    ax0 /= deg; ax1 /= deg; ax2 /= deg;
    float r0 = 0.f, r1 = 0.f, q0 = 0.f, q1 = 0.f;
    #pragma unroll 4
    for (int k = 0; k < HID_; k++) {
        float pre = sb[k] + xe0*s1s[k] + xe1*s1s[HID_+k] + xe2*s1s[2*HID_+k]
                          + ax0*s1n[k] + ax1*s1n[HID_+k] + ax2*s1n[2*HID_+k];
        float h = fmaxf(pre, 0.f);
        r0 += h * s2s[k];  r1 += h * s2s[HID_+k];
        q0 += h * s2n[k];  q1 += h * s2n[HID_+k];
    }
    g_rq[e*4+0] = r0; g_rq[e*4+1] = r1; g_rq[e*4+2] = q0; g_rq[e*4+3] = q1;
}

__global__ void k_gumbel(const float* __restrict__ b2) {
    int e = blockIdx.x * blockDim.x + threadIdx.x;
    if (e >= S3_) return;
    int E = g_E;
    if (e >= E) { g_yk[e] = 0xFFFFFFFFu; return; }
    int s = g_runstart[e], t = g_runstart[e+1];
    float deg = (float)(2*(t-s) + 1);
    float aq0 = g_rq[e*4+2], aq1 = g_rq[e*4+3];  // self loop
    for (int i = s; i < t; i++) {
        int slot = (int)g_sv_out[i];
        int fc = slot % FN_, j = slot / FN_;
        int e1 = g_inv[((j+1)%3)*FN_ + fc];
        int e2 = g_inv[((j+2)%3)*FN_ + fc];
        aq0 += g_rq[e1*4+2] + g_rq[e2*4+2];
        aq1 += g_rq[e1*4+3] + g_rq[e2*4+3];
    }
    float o0 = g_rq[e*4+0] + aq0/deg + b2[0];
    float o1 = g_rq[e*4+1] + aq1/deg + b2[1];
    float l0 = 1.f / (1.f + expf(-o0));           // sigmoid logits
    float l1 = 1.f / (1.f + expf(-o1));
    unsigned bb0 = tf_bits_part(2u*(unsigned)e);
    unsigned bb1 = tf_bits_part(2u*(unsigned)e + 1u);
    float U0 = __uint_as_float((bb0 >> 9) | 0x3F800000u) - 1.0f;
    float U1 = __uint_as_float((bb1 >> 9) | 0x3F800000u) - 1.0f;
    float gg0 = -logf(-logf(U0 + 1e-20f) + 1e-20f);
    float gg1 = -logf(-logf(U1 + 1e-20f) + 1e-20f);
    float z0 = (l0 + gg0) / 0.1f, z1 = (l1 + gg1) / 0.1f;
    float m  = fmaxf(z0, z1);
    float ez0 = expf(z0 - m), ez1 = expf(z1 - m);
    float y = ez0 / (ez0 + ez1);
    g_y[e] = y;
    g_yk[e] = (~__float_as_uint(y)) & 0x3FFFFFFFu;  // smaller key == larger y
}

// pick: find k-th crossing over nb buckets, update state, re-zero hist.
// kind: 0 key L1 (k=num, assign T)  1 key later (k=RK, OR)  2 idx L1 (k=RK, assign I)  3 idx last (k=RI, OR)
__device__ void dev_pick(int* hist, int nb, int shift, int kind) {
    __shared__ int sc[256];
    int t = threadIdx.x;
    int per = nb >> 8;
    int base = t * per;
    int vals[4];
    int local = 0;
    for (int j = 0; j < per; j++) { vals[j] = hist[base+j]; hist[base+j] = 0; local += vals[j]; }
    sc[t] = local;
    __syncthreads();
    for (int d = 1; d < 256; d <<= 1) {
        int v = (t >= d) ? sc[t-d] : 0;
        __syncthreads();
        sc[t] += v;
        __syncthreads();
    }
    int k = (kind == 0) ? g_num : (kind == 3) ? g_RI : g_RK;
    int cumex = sc[t] - local;
    if (cumex < k && sc[t] >= k) {
        int c = cumex;
        for (int j = 0; j < per; j++) {
            if (c + vals[j] >= k) {
                unsigned b = (unsigned)(base + j);
                int rem = k - c;
                if (kind == 0)      { g_T = b << shift; g_RK = rem; }
                else if (kind == 1) { g_T |= b << shift; g_RK = rem; }
                else if (kind == 2) { g_I = b << shift; g_RI = rem; }
                else                { g_I |= b << shift; }
                break;
            }
            c += vals[j];
        }
    }
}

// hist level + inline pick by the LAST finished block (threadfence + done counter)
__global__ void k_histpick(int shift, int matchshift, int bmask, int kind,
                           int idxlevel, int* hist) {
    __shared__ int sh[1024];
    __shared__ int slast;
    for (int j = threadIdx.x; j < 1024; j += 256) sh[j] = 0;
    __syncthreads();
    int E = g_E;
    unsigned T = g_T, I = g_I;
    int i = blockIdx.x * 256 + threadIdx.x;
    if (i < E) {
        unsigned key = g_yk[i];
        if (!idxlevel) {
            if ((key >> matchshift) == (T >> matchshift))
                atomicAdd(&sh[(key >> shift) & bmask], 1);
        } else {
            if (key == T && (((unsigned)i) >> matchshift) == (I >> matchshift))
                atomicAdd(&sh[(((unsigned)i) >> shift) & bmask], 1);
        }
    }
    __syncthreads();
    for (int j = threadIdx.x; j < 1024; j += 256)
        if (sh[j]) atomicAdd(&hist[j], sh[j]);
    __threadfence();
    if (threadIdx.x == 0) {
        unsigned d = atomicAdd(&g_done, 1u);
        slast = (d == gridDim.x - 1) ? 1 : 0;
    }
    __syncthreads();
    if (slast) {
        if (threadIdx.x == 0) g_done = 0;   // self-reset for next level / replay
        dev_pick(hist, bmask + 1, shift, kind);
    }
}

__global__ void k_sel() {
    int e = blockIdx.x * blockDim.x + threadIdx.x;
    if (e >= S3_) return;
    unsigned T = g_T, I = g_I;
    unsigned key = g_yk[e];
    g_selflag[e] = (e < g_E) && (key < T || (key == T && (unsigned)e <= I));
}

__global__ void k_cat() {
    int fc = blockIdx.x * blockDim.x + threadIdx.x;
    if (fc >= FN_) return;
    int m0 = g_selflag[g_inv[fc]];
    int m1 = g_selflag[g_inv[FN_ + fc]];
    int m2 = g_selflag[g_inv[2*FN_ + fc]];
    int pen = m0 + m1 + m2;
    int psi = m1 + 2*m2;
    int cat = (pen == 0) ? 0 : (pen == 1) ? 1 + psi : (pen == 2) ? 3 + psi : 7;
    #pragma unroll
    for (int k = 0; k < 8; k++) g_selflag[S3_ + k*FN_ + fc] = (k == cat) ? 1 : 0;
}

__device__ __forceinline__ void wtri(int row, int a, int b, int c) {
    g_nf[row*3+0] = a; g_nf[row*3+1] = b; g_nf[row*3+2] = c;
}

__global__ void k_faces(const int* __restrict__ face) {
    int fc = blockIdx.x * blockDim.x + threadIdx.x;
    if (fc >= FN_) return;
    int T0, C1, C2, T7; cat_counts(T0, C1, C2, T7);
    int num = g_num;
    int f0 = face[fc*3+0], f1 = face[fc*3+1], f2 = face[fc*3+2];
    int e0 = g_inv[fc], e1 = g_inv[FN_+fc], e2 = g_inv[2*FN_+fc];
    int m0 = g_selflag[e0], m1 = g_selflag[e1], m2 = g_selflag[e2];
    int p0 = VN_ + g_scan[e0], p1 = VN_ + g_scan[e1], p2 = VN_ + g_scan[e2];
    int pen = m0 + m1 + m2, psi = m1 + 2*m2;
    int cat = (pen == 0) ? 0 : (pen == 1) ? 1 + psi : (pen == 2) ? 3 + psi : 7;
    int pos = g_scan[S3_ + cat*FN_ + fc] - num;
    if (cat == 0) {
        wtri(pos, f0, f1, f2);
    } else if (cat <= 3) {                  // pen==1
        int g = pos - T0;
        int rA = T0 + g, rB = T0 + C1 + g;
        if (cat == 1)      { wtri(rA, f0, p0, f2); wtri(rB, p0, f1, f2); }
        else if (cat == 2) { wtri(rA, f1, p1, f0); wtri(rB, p1, f2, f0); }
        else               { wtri(rA, f2, p2, f1); wtri(rB, p2, f0, f1); }
    } else if (cat <= 6) {                  // pen==2
        int g = pos - (T0 + C1);
        int base2 = T0 + 2*C1;
        int rA = base2 + g, rB = base2 + C2 + g, rC = base2 + 2*C2 + g;
        if (cat == 4)      { wtri(rA, f0, p0, f2); wtri(rB, p0, f1, p1); wtri(rC, p0, p1, f2); }
        else if (cat == 5) { wtri(rA, f2, p2, f1); wtri(rB, p2, f0, p0); wtri(rC, p2, p0, f1); }
        else               { wtri(rA, f1, p1, f0); wtri(rB, p1, f2, p2); wtri(rC, p1, p2, f0); }
    } else {                                // pen==3
        int r = pos - (T0 + C1 + C2);
        int base3 = T0 + 2*C1 + 3*C2;
        wtri(base3 + r,        f0, p0, p2);
        wtri(base3 + T7 + r,   p0, f1, p1);
        wtri(base3 + 2*T7 + r, p0, p1, p2);
        wtri(base3 + 3*T7 + r, p1, f2, p2);
    }
}

// all three output sections in one launch (block-range dispatch)
__global__ void k_outputs(float* __restrict__ out) {
    int b = blockIdx.x;
    if (b < GS3) {
        int e = b * TPB + threadIdx.x;
        if (e >= EMAX_ || e >= g_E) return;
        int NF = nf_total();
        int NE = VN_ + g_num + 3*NF;
        int oM = 2*g_E + 3*NF + 2*NE;
        out[2*e]   = (float)g_en0[e];
        out[2*e+1] = (float)g_en1[e];
        float y  = g_y[e];
        float yh = g_selflag[e] ? 1.f : 0.f;
        out[oM + e] = (yh - y) + y;      // straight-through mask
    } else if (b < GS3 + GNF3) {
        int i = (b - GS3) * TPB + threadIdx.x;
        if (i >= 3*NFMAX_ || i >= 3*nf_total()) return;
        out[2*g_E + i] = (float)g_nf[i];
    } else {
        int t = (b - GS3 - GNF3) * TPB + threadIdx.x;
        if (t >= NEM_) return;
        int NF = nf_total();
        int NE = VN_ + g_num + 3*NF;
        if (t >= NE) return;
        int oNE = 2*g_E + 3*NF;
        int base = VN_ + g_num;
        int s, d;
        if (t < base) { s = t; d = t; }
        else {
            int u = t - base;
            if (u < NF)          { s = g_nf[u*3+0];        d = g_nf[u*3+1]; }
            else if (u < 2*NF)   { int r = u - NF;   s = g_nf[r*3+1]; d = g_nf[r*3+2]; }
            else                 { int r = u - 2*NF; s = g_nf[r*3+2]; d = g_nf[r*3+0]; }
        }
        out[oNE + t]      = (float)s;
        out[oNE + NE + t] = (float)d;
    }
}

// ---------------- host ----------------
extern "C" void kernel_launch(void* const* d_in, const int* in_sizes, int n_in,
                              void* d_out, int out_size) {
    const float* x    = (const float*)d_in[0];
    const int*   face = (const int*)d_in[1];
    const int*   divp = (const int*)d_in[4];
    const float* W1s  = (const float*)d_in[5];
    const float* W1n  = (const float*)d_in[6];
    const float* b1   = (const float*)d_in[7];
    const float* W2s  = (const float*)d_in[8];
    const float* W2n  = (const float*)d_in[9];
    const float* b2   = (const float*)d_in[10];
    float* out = (float*)d_out;

    void *tp, *psk_in, *psk_out, *psv_in, *psv_out;
    void *pselflag, *pscan, *phistK, *phistI;
    cudaGetSymbolAddress(&tp,      g_temp);
    cudaGetSymbolAddress(&psk_in,  g_sk_in);
    cudaGetSymbolAddress(&psk_out, g_sk_out);
    cudaGetSymbolAddress(&psv_in,  g_sv_in);
    cudaGetSymbolAddress(&psv_out, g_sv_out);
    cudaGetSymbolAddress(&pselflag,g_selflag);
    cudaGetSymbolAddress(&pscan,   g_scan);
    cudaGetSymbolAddress(&phistK,  g_histK);
    cudaGetSymbolAddress(&phistI,  g_histI);
    cudaStream_t st = 0;
    size_t tb;

    k_build_keys<<<GS3, TPB, 0, st>>>(face);

    tb = sizeof(g_temp);
    cub::DeviceRadixSort::SortPairs(tp, tb,
        (const unsigned*)psk_in, (unsigned*)psk_out,
        (const unsigned*)psv_in, (unsigned*)psv_out, S3_, 0, 32, st);

    k_head<<<GS3, TPB, 0, st>>>();
    k_tiny1<<<1, 1024, 0, st>>>();
    k_unique<<<GS3, TPB, 0, st>>>(x, divp);
    k_gnn1<<<GS3, TPB, 0, st>>>(W1s, W1n, b1, W2s, W2n);
    k_gumbel<<<GS3, TPB, 0, st>>>(b2);

    // radix-select: key 3x10 bits, tie-index 10+9 bits; pick fused into each level
    k_histpick<<<GS3, TPB, 0, st>>>(20, 30, 1023, 0, 0, (int*)phistK);
    k_histpick<<<GS3, TPB, 0, st>>>(10, 20, 1023, 1, 0, (int*)phistK);
    k_histpick<<<GS3, TPB, 0, st>>>( 0, 10, 1023, 1, 0, (int*)phistK);
    k_histpick<<<GS3, TPB, 0, st>>>( 9, 19, 1023, 2, 1, (int*)phistI);
    k_histpick<<<GS3, TPB, 0, st>>>( 0,  9,  511, 3, 1, (int*)phistI);
    k_sel<<<GS3, TPB, 0, st>>>();

    k_cat<<<GF, TPB, 0, st>>>();
    // one combined scan: sel (pool ranks) + 8-category face flags (R7-proven)
    tb = sizeof(g_temp);
    cub::DeviceScan::ExclusiveSum(tp, tb, (const int*)pselflag, (int*)pscan, SF_, st);
    k_faces<<<GF, TPB, 0, st>>>(face);

    k_outputs<<<GS3 + GNF3 + GNE, TPB, 0, st>>>(out);
}

// round 10
// speedup vs baseline: 1.2932x; 1.0101x over previous
#include <cuda_runtime.h>
#include <cstdint>
#include <cub/cub.cuh>

#define VN_    50000
#define FN_    100000
#define S3_    (3*FN_)
#define EMAX_  S3_
#define HID_   256
#define NFMAX_ (4*FN_)
#define PEMAX_ ((S3_/5)+64)
#define NEM_   (VN_ + PEMAX_ + 3*NFMAX_)
#define SF_    (S3_ + 8*FN_)          // combined sel+flag8 scan length
#define TPB    256
#define GS3    ((S3_ + TPB - 1)/TPB)  // 1172
#define GF     ((FN_ + TPB - 1)/TPB)
#define GNE    ((NEM_ + TPB - 1)/TPB)
#define GNF3   ((3*NFMAX_ + TPB - 1)/TPB)
#define NCHS   GS3

// ---------------- static device scratch (no allocation allowed) ----------------
__device__ unsigned g_sk_in[S3_], g_sk_out[S3_], g_sv_in[S3_], g_sv_out[S3_];
__device__ int g_rank[S3_], g_inv[S3_];
__device__ int g_chU[NCHS], g_offU[NCHS];
__device__ int g_runstart[EMAX_+1];
__device__ int g_en0[EMAX_], g_en1[EMAX_];
__device__ float g_xe[EMAX_*4];      // padded to 4 floats/edge for vector loads
__device__ float g_rq[EMAX_*4];      // r0,r1,q0,q1 per edge (float4)
__device__ float g_y[EMAX_];
__device__ unsigned g_yk[S3_];       // 30-bit selection keys (~float_bits(y))
__device__ int g_selflag[SF_];       // [0,S3_): sel ; [S3_,S3_+8FN): flag8
__device__ int g_scan[SF_];          // exclusive scan of g_selflag
__device__ int g_nf[3*NFMAX_];
__device__ int g_histK[1024];        // key-select histogram (picks re-zero)
__device__ int g_histI[1024];        // index-select histogram (picks re-zero)
__device__ unsigned g_T;             // threshold key (30-bit)
__device__ int g_RK;                 // remaining count within key threshold
__device__ unsigned g_I;             // tie threshold index I* (19-bit)
__device__ int g_RI;
__device__ unsigned g_done = 0;      // last-block-done counter (self-resets)
__device__ int g_E, g_num;
__device__ unsigned char g_temp[48u<<20];

// ---------------- threefry2x32, key = (0,42), JAX-exact ----------------
__device__ __forceinline__ unsigned rotl32(unsigned v, int d) {
    return (v << d) | (v >> (32 - d));
}
__device__ __forceinline__ void threefry_0_42(unsigned x0, unsigned x1,
                                              unsigned& o0, unsigned& o1) {
    const unsigned k0 = 0u, k1 = 42u;
    const unsigned ks2 = k0 ^ k1 ^ 0x1BD11BDAu;
    x0 += k0; x1 += k1;
#define TF4(a,b,c,d) \
    x0 += x1; x1 = rotl32(x1,a); x1 ^= x0; \
    x0 += x1; x1 = rotl32(x1,b); x1 ^= x0; \
    x0 += x1; x1 = rotl32(x1,c); x1 ^= x0; \
    x0 += x1; x1 = rotl32(x1,d); x1 ^= x0;
    TF4(13,15,26,6);   x0 += k1;  x1 += ks2 + 1u;
    TF4(17,29,16,24);  x0 += ks2; x1 += k0  + 2u;
    TF4(13,15,26,6);   x0 += k0;  x1 += k1  + 3u;
    TF4(17,29,16,24);  x0 += k1;  x1 += ks2 + 4u;
    TF4(13,15,26,6);   x0 += ks2; x1 += k0  + 5u;
#undef TF4
    o0 = x0; o1 = x1;
}
// Partitionable-threefry (JAX >= 0.5 default): bits[i] = xor(threefry((0,42),(0,i)))
__device__ __forceinline__ unsigned tf_bits_part(unsigned i) {
    unsigned o0, o1;
    threefry_0_42(0u, i, o0, o1);
    return o0 ^ o1;
}

// exclusive in-block binary prefix over 256 threads; also returns block total
__device__ __forceinline__ int blk_prefix(int flag, int* wsum, int* total) {
    unsigned m = __ballot_sync(0xFFFFFFFFu, flag != 0);
    int lane = threadIdx.x & 31, w = threadIdx.x >> 5;
    int excl = __popc(m & ((1u << lane) - 1u));
    if (lane == 0) wsum[w] = __popc(m);
    __syncthreads();
    int off = 0, tot = 0;
    #pragma unroll
    for (int j = 0; j < 8; j++) { int v = wsum[j]; tot += v; if (j < w) off += v; }
    *total = tot;
    __syncthreads();
    return excl + off;
}

// derived category counts from the combined scan
__device__ __forceinline__ void cat_counts(int& T0, int& C1, int& C2, int& T7) {
    int num = g_num;
    int P1 = g_scan[S3_ +   FN_] - num;
    int P4 = g_scan[S3_ + 4*FN_] - num;
    int P7 = g_scan[S3_ + 7*FN_] - num;
    T0 = P1; C1 = P4 - P1; C2 = P7 - P4; T7 = FN_ - P7;
}
__device__ __forceinline__ int nf_total() {
    int T0, C1, C2, T7; cat_counts(T0, C1, C2, T7);
    return T0 + 2*C1 + 3*C2 + 4*T7;
}

// ---------------- kernels ----------------
__global__ void k_build_keys(const int* __restrict__ face) {
    int i = blockIdx.x * blockDim.x + threadIdx.x;
    if (i >= S3_) return;
    int blk = i / FN_, fc = i - blk * FN_;
    int a, b;
    if (blk == 0)      { a = face[fc*3+0]; b = face[fc*3+1]; }
    else if (blk == 1) { a = face[fc*3+1]; b = face[fc*3+2]; }
    else               { a = face[fc*3+2]; b = face[fc*3+0]; }
    int lo = min(a, b), hi = max(a, b);
    int key = (int)((unsigned)lo * (unsigned)VN_ + (unsigned)hi); // int32 wrap like JAX
    g_sk_in[i] = (unsigned)key ^ 0x80000000u;  // signed order under unsigned radix
    g_sv_in[i] = (unsigned)i;
}

// head flags + in-chunk inclusive prefix + chunk totals
__global__ void k_head() {
    __shared__ int wsum[8];
    int i = blockIdx.x * blockDim.x + threadIdx.x;
    int flag = (i < S3_) && (i == 0 || g_sk_out[i] != g_sk_out[i-1]);
    int tot;
    int excl = blk_prefix(flag, wsum, &tot);
    if (i < S3_) g_rank[i] = excl + flag;   // in-chunk inclusive
    if (threadIdx.x == 0) g_chU[blockIdx.x] = tot;
}

// single-block exclusive scan of chunk totals
__global__ void k_tiny1() {
    __shared__ int part[1024];
    int t = threadIdx.x;
    int a0 = (2*t   < NCHS) ? g_chU[2*t]   : 0;
    int a1 = (2*t+1 < NCHS) ? g_chU[2*t+1] : 0;
    part[t] = a0 + a1;
    __syncthreads();
    for (int d = 1; d < 1024; d <<= 1) {
        int v = (t >= d) ? part[t-d] : 0;
        __syncthreads();
        part[t] += v;
        __syncthreads();
    }
    int base = t ? part[t-1] : 0;
    if (2*t   < NCHS) g_offU[2*t]   = base;
    if (2*t+1 < NCHS) g_offU[2*t+1] = base + a0;
}

// unique + inverse map + scalars + edge-node endpoints + xe, fused
__global__ void k_unique(const float* __restrict__ x, const int* __restrict__ divp) {
    int i = blockIdx.x * blockDim.x + threadIdx.x;
    if (i >= S3_) return;
    int r = g_offU[blockIdx.x] + g_rank[i];   // global inclusive rank
    int flag = (i == 0 || g_sk_out[i] != g_sk_out[i-1]);
    if (flag) {
        int e = r - 1;
        g_runstart[e] = i;
        int k = (int)(g_sk_out[i] ^ 0x80000000u);
        int q = k / VN_, rm = k % VN_;     // C trunc -> numpy floor fixup
        if (rm < 0) { rm += VN_; q -= 1; }
        g_en0[e] = q; g_en1[e] = rm;
        int i0 = (q < 0) ? q + VN_ : q;    // JAX gather: negative wrap, then clamp
        if (i0 < 0) i0 = 0;
        if (i0 >= VN_) i0 = VN_ - 1;
        float4 v;
        v.x = 0.5f * (x[i0*3+0] + x[rm*3+0]);
        v.y = 0.5f * (x[i0*3+1] + x[rm*3+1]);
        v.z = 0.5f * (x[i0*3+2] + x[rm*3+2]);
        v.w = 0.f;
        *(float4*)&g_xe[e*4] = v;
    }
    g_inv[g_sv_out[i]] = r - 1;
    if (i == S3_ - 1) { g_E = r; g_runstart[r] = S3_; g_num = r / divp[0]; }
}

__global__ void k_gnn1(const float* __restrict__ W1s, const float* __restrict__ W1n,
                       const float* __restrict__ b1,  const float* __restrict__ W2s,
                       const float* __restrict__ W2n) {
    __shared__ float s1s[3*HID_], s1n[3*HID_], sb[HID_], s2s[2*HID_], s2n[2*HID_];
    for (int i = threadIdx.x; i < 3*HID_; i += blockDim.x) { s1s[i] = W1s[i]; s1n[i] = W1n[i]; }
    for (int i = threadIdx.x; i < HID_;   i += blockDim.x) {
        sb[i] = b1[i];
        s2s[i] = W2s[i*2+0]; s2s[HID_+i] = W2s[i*2+1];
        s2n[i] = W2n[i*2+0]; s2n[HID_+i] = W2n[i*2+1];
    }
    __syncthreads();
    int e = blockIdx.x * blockDim.x + threadIdx.x;
    if (e >= EMAX_ || e >= g_E) return;
    int s = g_runstart[e], t = g_runstart[e+1];
    float deg = (float)(2*(t-s) + 1);
    float4 xev = *(const float4*)&g_xe[e*4];
    float xe0 = xev.x, xe1 = xev.y, xe2 = xev.z;
    float ax0 = xe0, ax1 = xe1, ax2 = xe2;   // self loop
    for (int i = s; i < t; i++) {
        int slot = (int)g_sv_out[i];
        int fc = slot % FN_, j = slot / FN_;
        int e1 = g_inv[((j+1)%3)*FN_ + fc];
        int e2 = g_inv[((j+2)%3)*FN_ + fc];
        float4 v1 = *(const float4*)&g_xe[e1*4];
        float4 v2 = *(const float4*)&g_xe[e2*4];
        ax0 += v1.x + v2.x;
        ax1 += v1.y + v2.y;
        ax2 += v1.z + v2.z;
    }
    ax0 /= deg; ax1 /= deg; ax2 /= deg;
    float r0 = 0.f, r1 = 0.f, q0 = 0.f, q1 = 0.f;
    // k in groups of 4; LDS.128 weight loads; per-k expression identical to the
    // scalar version => identical FFMA chains => bit-identical results.
    for (int k4 = 0; k4 < HID_; k4 += 4) {
        float4 vb  = *(const float4*)&sb[k4];
        float4 a0v = *(const float4*)&s1s[k4];
        float4 a1v = *(const float4*)&s1s[HID_ + k4];
        float4 a2v = *(const float4*)&s1s[2*HID_ + k4];
        float4 n0v = *(const float4*)&s1n[k4];
        float4 n1v = *(const float4*)&s1n[HID_ + k4];
        float4 n2v = *(const float4*)&s1n[2*HID_ + k4];
        float4 w0v = *(const float4*)&s2s[k4];
        float4 w1v = *(const float4*)&s2s[HID_ + k4];
        float4 u0v = *(const float4*)&s2n[k4];
        float4 u1v = *(const float4*)&s2n[HID_ + k4];
        #define GNN_STEP(c) { \
            float pre = vb.c + xe0*a0v.c + xe1*a1v.c + xe2*a2v.c \
                             + ax0*n0v.c + ax1*n1v.c + ax2*n2v.c; \
            float h = fmaxf(pre, 0.f); \
            r0 += h * w0v.c;  r1 += h * w1v.c; \
            q0 += h * u0v.c;  q1 += h * u1v.c; }
        GNN_STEP(x) GNN_STEP(y) GNN_STEP(z) GNN_STEP(w)
        #undef GNN_STEP
    }
    float4 outv; outv.x = r0; outv.y = r1; outv.z = q0; outv.w = q1;
    *(float4*)&g_rq[e*4] = outv;
}

__global__ void k_gumbel(const float* __restrict__ b2) {
    int e = blockIdx.x * blockDim.x + threadIdx.x;
    if (e >= S3_) return;
    int E = g_E;
    if (e >= E) { g_yk[e] = 0xFFFFFFFFu; return; }
    int s = g_runstart[e], t = g_runstart[e+1];
    float deg = (float)(2*(t-s) + 1);
    float4 rqv = *(const float4*)&g_rq[e*4];
    float aq0 = rqv.z, aq1 = rqv.w;              // self loop
    for (int i = s; i < t; i++) {
        int slot = (int)g_sv_out[i];
        int fc = slot % FN_, j = slot / FN_;
        int e1 = g_inv[((j+1)%3)*FN_ + fc];
        int e2 = g_inv[((j+2)%3)*FN_ + fc];
        float4 v1 = *(const float4*)&g_rq[e1*4];
        float4 v2 = *(const float4*)&g_rq[e2*4];
        aq0 += v1.z + v2.z;
        aq1 += v1.w + v2.w;
    }
    float o0 = rqv.x + aq0/deg + b2[0];
    float o1 = rqv.y + aq1/deg + b2[1];
    float l0 = 1.f / (1.f + expf(-o0));           // sigmoid logits
    float l1 = 1.f / (1.f + expf(-o1));
    unsigned bb0 = tf_bits_part(2u*(unsigned)e);
    unsigned bb1 = tf_bits_part(2u*(unsigned)e + 1u);
    float U0 = __uint_as_float((bb0 >> 9) | 0x3F800000u) - 1.0f;
    float U1 = __uint_as_float((bb1 >> 9) | 0x3F800000u) - 1.0f;
    float gg0 = -logf(-logf(U0 + 1e-20f) + 1e-20f);
    float gg1 = -logf(-logf(U1 + 1e-20f) + 1e-20f);
    float z0 = (l0 + gg0) / 0.1f, z1 = (l1 + gg1) / 0.1f;
    float m  = fmaxf(z0, z1);
    float ez0 = expf(z0 - m), ez1 = expf(z1 - m);
    float y = ez0 / (ez0 + ez1);
    g_y[e] = y;
    g_yk[e] = (~__float_as_uint(y)) & 0x3FFFFFFFu;  // smaller key == larger y
}

// pick: find k-th crossing over nb buckets, update state, re-zero hist.
__device__ void dev_pick(int* hist, int nb, int shift, int kind) {
    __shared__ int sc[256];
    int t = threadIdx.x;
    int per = nb >> 8;
    int base = t * per;
    int vals[4];
    int local = 0;
    for (int j = 0; j < per; j++) { vals[j] = hist[base+j]; hist[base+j] = 0; local += vals[j]; }
    sc[t] = local;
    __syncthreads();
    for (int d = 1; d < 256; d <<= 1) {
        int v = (t >= d) ? sc[t-d] : 0;
        __syncthreads();
        sc[t] += v;
        __syncthreads();
    }
    int k = (kind == 0) ? g_num : (kind == 3) ? g_RI : g_RK;
    int cumex = sc[t] - local;
    if (cumex < k && sc[t] >= k) {
        int c = cumex;
        for (int j = 0; j < per; j++) {
            if (c + vals[j] >= k) {
                unsigned b = (unsigned)(base + j);
                int rem = k - c;
                if (kind == 0)      { g_T = b << shift; g_RK = rem; }
                else if (kind == 1) { g_T |= b << shift; g_RK = rem; }
                else if (kind == 2) { g_I = b << shift; g_RI = rem; }
                else                { g_I |= b << shift; }
                break;
            }
            c += vals[j];
        }
    }
}

// hist level + inline pick by the LAST finished block
__global__ void k_histpick(int shift, int matchshift, int bmask, int kind,
                           int idxlevel, int* hist) {
    __shared__ int sh[1024];
    __shared__ int slast;
    for (int j = threadIdx.x; j < 1024; j += 256) sh[j] = 0;
    __syncthreads();
    int E = g_E;
    unsigned T = g_T, I = g_I;
    int i = blockIdx.x * 256 + threadIdx.x;
    if (i < E) {
        unsigned key = g_yk[i];
        if (!idxlevel) {
            if ((key >> matchshift) == (T >> matchshift))
                atomicAdd(&sh[(key >> shift) & bmask], 1);
        } else {
            if (key == T && (((unsigned)i) >> matchshift) == (I >> matchshift))
                atomicAdd(&sh[(((unsigned)i) >> shift) & bmask], 1);
        }
    }
    __syncthreads();
    for (int j = threadIdx.x; j < 1024; j += 256)
        if (sh[j]) atomicAdd(&hist[j], sh[j]);
    __threadfence();
    if (threadIdx.x == 0) {
        unsigned d = atomicAdd(&g_done, 1u);
        slast = (d == gridDim.x - 1) ? 1 : 0;
    }
    __syncthreads();
    if (slast) {
        if (threadIdx.x == 0) g_done = 0;   // self-reset for next level / replay
        dev_pick(hist, bmask + 1, shift, kind);
    }
}

__global__ void k_sel() {
    int e = blockIdx.x * blockDim.x + threadIdx.x;
    if (e >= S3_) return;
    unsigned T = g_T, I = g_I;
    unsigned key = g_yk[e];
    g_selflag[e] = (e < g_E) && (key < T || (key == T && (unsigned)e <= I));
}

__global__ void k_cat() {
    int fc = blockIdx.x * blockDim.x + threadIdx.x;
    if (fc >= FN_) return;
    int m0 = g_selflag[g_inv[fc]];
    int m1 = g_selflag[g_inv[FN_ + fc]];
    int m2 = g_selflag[g_inv[2*FN_ + fc]];
    int pen = m0 + m1 + m2;
    int psi = m1 + 2*m2;
    int cat = (pen == 0) ? 0 : (pen == 1) ? 1 + psi : (pen == 2) ? 3 + psi : 7;
    #pragma unroll
    for (int k = 0; k < 8; k++) g_selflag[S3_ + k*FN_ + fc] = (k == cat) ? 1 : 0;
}

__device__ __forceinline__ void wtri(int row, int a, int b, int c) {
    g_nf[row*3+0] = a; g_nf[row*3+1] = b; g_nf[row*3+2] = c;
}

__global__ void k_faces(const int* __restrict__ face) {
    int fc = blockIdx.x * blockDim.x + threadIdx.x;
    if (fc >= FN_) return;
    int T0, C1, C2, T7; cat_counts(T0, C1, C2, T7);
    int num = g_num;
    int f0 = face[fc*3+0], f1 = face[fc*3+1], f2 = face[fc*3+2];
    int e0 = g_inv[fc], e1 = g_inv[FN_+fc], e2 = g_inv[2*FN_+fc];
    int m0 = g_selflag[e0], m1 = g_selflag[e1], m2 = g_selflag[e2];
    int p0 = VN_ + g_scan[e0], p1 = VN_ + g_scan[e1], p2 = VN_ + g_scan[e2];
    int pen = m0 + m1 + m2, psi = m1 + 2*m2;
    int cat = (pen == 0) ? 0 : (pen == 1) ? 1 + psi : (pen == 2) ? 3 + psi : 7;
    int pos = g_scan[S3_ + cat*FN_ + fc] - num;
    if (cat == 0) {
        wtri(pos, f0, f1, f2);
    } else if (cat <= 3) {                  // pen==1
        int g = pos - T0;
        int rA = T0 + g, rB = T0 + C1 + g;
        if (cat == 1)      { wtri(rA, f0, p0, f2); wtri(rB, p0, f1, f2); }
        else if (cat == 2) { wtri(rA, f1, p1, f0); wtri(rB, p1, f2, f0); }
        else               { wtri(rA, f2, p2, f1); wtri(rB, p2, f0, f1); }
    } else if (cat <= 6) {                  // pen==2
        int g = pos - (T0 + C1);
        int base2 = T0 + 2*C1;
        int rA = base2 + g, rB = base2 + C2 + g, rC = base2 + 2*C2 + g;
        if (cat == 4)      { wtri(rA, f0, p0, f2); wtri(rB, p0, f1, p1); wtri(rC, p0, p1, f2); }
        else if (cat == 5) { wtri(rA, f2, p2, f1); wtri(rB, p2, f0, p0); wtri(rC, p2, p0, f1); }
        else               { wtri(rA, f1, p1, f0); wtri(rB, p1, f2, p2); wtri(rC, p1, p2, f0); }
    } else {                                // pen==3
        int r = pos - (T0 + C1 + C2);
        int base3 = T0 + 2*C1 + 3*C2;
        wtri(base3 + r,        f0, p0, p2);
        wtri(base3 + T7 + r,   p0, f1, p1);
        wtri(base3 + 2*T7 + r, p0, p1, p2);
        wtri(base3 + 3*T7 + r, p1, f2, p2);
    }
}

// all three output sections in one launch (block-range dispatch)
__global__ void k_outputs(float* __restrict__ out) {
    int b = blockIdx.x;
    if (b < GS3) {
        int e = b * TPB + threadIdx.x;
        if (e >= EMAX_ || e >= g_E) return;
        int NF = nf_total();
        int NE = VN_ + g_num + 3*NF;
        int oM = 2*g_E + 3*NF + 2*NE;
        out[2*e]   = (float)g_en0[e];
        out[2*e+1] = (float)g_en1[e];
        float y  = g_y[e];
        float yh = g_selflag[e] ? 1.f : 0.f;
        out[oM + e] = (yh - y) + y;      // straight-through mask
    } else if (b < GS3 + GNF3) {
        int i = (b - GS3) * TPB + threadIdx.x;
        if (i >= 3*NFMAX_ || i >= 3*nf_total()) return;
        out[2*g_E + i] = (float)g_nf[i];
    } else {
        int t = (b - GS3 - GNF3) * TPB + threadIdx.x;
        if (t >= NEM_) return;
        int NF = nf_total();
        int NE = VN_ + g_num + 3*NF;
        if (t >= NE) return;
        int oNE = 2*g_E + 3*NF;
        int base = VN_ + g_num;
        int s, d;
        if (t < base) { s = t; d = t; }
        else {
            int u = t - base;
            if (u < NF)          { s = g_nf[u*3+0];        d = g_nf[u*3+1]; }
            else if (u < 2*NF)   { int r = u - NF;   s = g_nf[r*3+1]; d = g_nf[r*3+2]; }
            else                 { int r = u - 2*NF; s = g_nf[r*3+2]; d = g_nf[r*3+0]; }
        }
        out[oNE + t]      = (float)s;
        out[oNE + NE + t] = (float)d;
    }
}

// ---------------- host ----------------
extern "C" void kernel_launch(void* const* d_in, const int* in_sizes, int n_in,
                              void* d_out, int out_size) {
    const float* x    = (const float*)d_in[0];
    const int*   face = (const int*)d_in[1];
    const int*   divp = (const int*)d_in[4];
    const float* W1s  = (const float*)d_in[5];
    const float* W1n  = (const float*)d_in[6];
    const float* b1   = (const float*)d_in[7];
    const float* W2s  = (const float*)d_in[8];
    const float* W2n  = (const float*)d_in[9];
    const float* b2   = (const float*)d_in[10];
    float* out = (float*)d_out;

    void *tp, *psk_in, *psk_out, *psv_in, *psv_out;
    void *pselflag, *pscan, *phistK, *phistI;
    cudaGetSymbolAddress(&tp,      g_temp);
    cudaGetSymbolAddress(&psk_in,  g_sk_in);
    cudaGetSymbolAddress(&psk_out, g_sk_out);
    cudaGetSymbolAddress(&psv_in,  g_sv_in);
    cudaGetSymbolAddress(&psv_out, g_sv_out);
    cudaGetSymbolAddress(&pselflag,g_selflag);
    cudaGetSymbolAddress(&pscan,   g_scan);
    cudaGetSymbolAddress(&phistK,  g_histK);
    cudaGetSymbolAddress(&phistI,  g_histI);
    cudaStream_t st = 0;
    size_t tb;

    k_build_keys<<<GS3, TPB, 0, st>>>(face);

    tb = sizeof(g_temp);
    cub::DeviceRadixSort::SortPairs(tp, tb,
        (const unsigned*)psk_in, (unsigned*)psk_out,
        (const unsigned*)psv_in, (unsigned*)psv_out, S3_, 0, 32, st);

    k_head<<<GS3, TPB, 0, st>>>();
    k_tiny1<<<1, 1024, 0, st>>>();
    k_unique<<<GS3, TPB, 0, st>>>(x, divp);
    k_gnn1<<<GS3, TPB, 0, st>>>(W1s, W1n, b1, W2s, W2n);
    k_gumbel<<<GS3, TPB, 0, st>>>(b2);

    // radix-select: key 3x10 bits, tie-index 10+9 bits; pick fused into each level
    k_histpick<<<GS3, TPB, 0, st>>>(20, 30, 1023, 0, 0, (int*)phistK);
    k_histpick<<<GS3, TPB, 0, st>>>(10, 20, 1023, 1, 0, (int*)phistK);
    k_histpick<<<GS3, TPB, 0, st>>>( 0, 10, 1023, 1, 0, (int*)phistK);
    k_histpick<<<GS3, TPB, 0, st>>>( 9, 19, 1023, 2, 1, (int*)phistI);
    k_histpick<<<GS3, TPB, 0, st>>>( 0,  9,  511, 3, 1, (int*)phistI);
    k_sel<<<GS3, TPB, 0, st>>>();

    k_cat<<<GF, TPB, 0, st>>>();
    // one combined scan: sel (pool ranks) + 8-category face flags
    tb = sizeof(g_temp);
    cub::DeviceScan::ExclusiveSum(tp, tb, (const int*)pselflag, (int*)pscan, SF_, st);
    k_faces<<<GF, TPB, 0, st>>>(face);

    k_outputs<<<GS3 + GNF3 + GNE, TPB, 0, st>>>(out);
}